// round 14
// baseline (speedup 1.0000x reference)
#include <cuda_runtime.h>
#include <cstdint>

#define NN 100000
#define EE 1600000
#define HH 128
#define H3 384
#define LL 3

// ---------------- scratch (static device globals; no allocation) ----------------
__device__ __align__(256) float g_m[(size_t)NN * HH];     // m = x @ W[l]
__device__ __align__(256) float g_agg[(size_t)NN * HH];   // scatter-add target
__device__ __align__(256) float g_gi[(size_t)NN * H3];    // agg @ w_ih^T + b_ih
__device__ __align__(256) float g_gh[(size_t)NN * H3];    // x   @ w_hh^T + b_hh
__device__ __align__(256) float g_x[(size_t)NN * HH];     // hidden state ping buffer
__device__ int g_idx64;
__device__ __align__(256) int g_src[EE];
__device__ __align__(256) int g_dst[EE];

// bf16 hi/lo split weights, stored [n][k] (k contiguous, K=128)
__device__ __align__(256) unsigned short g_B1hi[3 * HH * HH];
__device__ __align__(256) unsigned short g_B1lo[3 * HH * HH];
__device__ __align__(256) unsigned short g_Bihhi[H3 * HH];
__device__ __align__(256) unsigned short g_Bihlo[H3 * HH];
__device__ __align__(256) unsigned short g_Bhhhi[H3 * HH];
__device__ __align__(256) unsigned short g_Bhhlo[H3 * HH];

// ---------------- bf16 split helpers ----------------
__device__ __forceinline__ unsigned bf16h(float f) {
    unsigned x = __float_as_uint(f);
    return (x + 0x7fffu + ((x >> 16) & 1u)) >> 16;   // rn-even to bf16 bits
}
__device__ __forceinline__ float bf16f(unsigned b) { return __uint_as_float(b << 16); }

__device__ __forceinline__ uint32_t smem_u32(const void* p) {
    uint32_t a;
    asm("{ .reg .u64 t; cvta.to.shared.u64 t, %1; cvt.u32.u64 %0, t; }" : "=r"(a) : "l"(p));
    return a;
}
__device__ __forceinline__ void cpasync16(uint32_t dst, const void* src) {
    asm volatile("cp.async.cg.shared.global [%0], [%1], 16;" :: "r"(dst), "l"(src));
}
#define CP_COMMIT() asm volatile("cp.async.commit_group;" ::: "memory")
#define CP_WAIT1()  asm volatile("cp.async.wait_group 1;" ::: "memory")
#define CP_WAIT0()  asm volatile("cp.async.wait_group 0;" ::: "memory")

__device__ __forceinline__ void ldsm_x4(unsigned* r, uint32_t addr) {
    asm volatile("ldmatrix.sync.aligned.m8n8.x4.shared.b16 {%0,%1,%2,%3}, [%4];"
        : "=r"(r[0]), "=r"(r[1]), "=r"(r[2]), "=r"(r[3]) : "r"(addr));
}
__device__ __forceinline__ void ldsm_x2(unsigned* r, uint32_t addr) {
    asm volatile("ldmatrix.sync.aligned.m8n8.x2.shared.b16 {%0,%1}, [%2];"
        : "=r"(r[0]), "=r"(r[1]) : "r"(addr));
}

// ---------------- detect edge_index dtype ----------------
__global__ void detect_idx_kernel(const int* __restrict__ ei32) {
    int bad = 0;
    for (int i = threadIdx.x; i < 4096; i += blockDim.x)
        if ((i & 1) && ei32[i] != 0) bad = 1;
    bad = __syncthreads_or(bad);
    if (threadIdx.x == 0) g_idx64 = bad ? 0 : 1;
}

// ---------------- decode edge_index -> int32 src/dst ----------------
__global__ __launch_bounds__(256) void prep_idx_kernel(const void* __restrict__ ei,
                                                       int* __restrict__ src,
                                                       int* __restrict__ dst) {
    int e = blockIdx.x * blockDim.x + threadIdx.x;
    if (e >= EE) return;
    int s, d;
    if (g_idx64) {
        const long long* p = (const long long*)ei;
        s = (int)p[e]; d = (int)p[EE + e];
    } else {
        const int* p = (const int*)ei;
        s = p[e]; d = p[EE + e];
    }
    if ((unsigned)s >= NN) s = 0;
    if ((unsigned)d >= NN) d = 0;
    src[e] = s; dst[e] = d;
}

// ---------------- split weight[l] ([k][n]) -> transposed [n][k] hi/lo ----------------
__global__ void split_w1_kernel(const float* __restrict__ w,
                                unsigned short* __restrict__ hi,
                                unsigned short* __restrict__ lo) {
    int i = blockIdx.x * blockDim.x + threadIdx.x;
    if (i >= 3 * HH * HH) return;
    int l = i >> 14, rem = i & 16383;
    int k = rem >> 7, n = rem & 127;
    float f = w[i];
    unsigned h = bf16h(f);
    unsigned lb = bf16h(f - bf16f(h));
    int o = l * HH * HH + n * HH + k;
    hi[o] = (unsigned short)h;
    lo[o] = (unsigned short)lb;
}

// ---------------- split BOTH gru weight matrices in one launch ----------------
__global__ void split_w2_kernel(const float* __restrict__ wa, const float* __restrict__ wb,
                                unsigned short* __restrict__ hia, unsigned short* __restrict__ loa,
                                unsigned short* __restrict__ hib, unsigned short* __restrict__ lob) {
    int i = blockIdx.x * blockDim.x + threadIdx.x;
    int count = H3 * HH;
    if (i < count) {
        float f = wa[i];
        unsigned h = bf16h(f);
        hia[i] = (unsigned short)h;
        loa[i] = (unsigned short)bf16h(f - bf16f(h));
    } else if (i < 2 * count) {
        int j = i - count;
        float f = wb[j];
        unsigned h = bf16h(f);
        hib[j] = (unsigned short)h;
        lob[j] = (unsigned short)bf16h(f - bf16f(h));
    }
}

// ---------------- zero buffer ----------------
__global__ void zero_kernel(float4* __restrict__ p, int n4) {
    int i = blockIdx.x * blockDim.x + threadIdx.x;
    if (i < n4) p[i] = make_float4(0.f, 0.f, 0.f, 0.f);
}

// ---------------- persistent-A tensor GEMM (mma.sync bf16 3-term split) -------------
// A fp32 [nrows][128] staged ONCE per CTA as bf16 hi/lo; loops over all output
// column tiles of up to two (B, C, bias) sets. B pre-split bf16 [n][k].
// 8 warps (4M x 2N), warp tile 32x32, K=128 resident, cp.async dbl-buffered B,
// ldmatrix fragment loads.
#define SAW 68                       // smem row stride in words (64 data + 4 pad)
#define SA  (128 * SAW)              // one 128-row A array (words)
#define SB  (64 * SAW)               // one 64-row B array (words)
#define OFF_ALO SA
#define OFF_B   (2 * SA)
#define SMEM_WORDS (2 * SA + 4 * SB)
#define SMEM_BYTES (SMEM_WORDS * 4)  // 139264

__device__ __forceinline__ void mma_bf16(float* c, const unsigned* a, unsigned b0, unsigned b1) {
    asm volatile(
        "mma.sync.aligned.m16n8k16.row.col.f32.bf16.bf16.f32 "
        "{%0,%1,%2,%3}, {%4,%5,%6,%7}, {%8,%9}, {%0,%1,%2,%3};"
        : "+f"(c[0]), "+f"(c[1]), "+f"(c[2]), "+f"(c[3])
        : "r"(a[0]), "r"(a[1]), "r"(a[2]), "r"(a[3]), "r"(b0), "r"(b1));
}

__global__ __launch_bounds__(256) void mma_gemm_persist(
    const float* __restrict__ A, int nrows,
    const unsigned short* __restrict__ B1h, const unsigned short* __restrict__ B1l,
    const float* __restrict__ bias1, float* __restrict__ C1, int ncols1, int nt1,
    const unsigned short* __restrict__ B2h, const unsigned short* __restrict__ B2l,
    const float* __restrict__ bias2, float* __restrict__ C2, int ncols2, int nt2)
{
    extern __shared__ __align__(16) unsigned sm[];
    unsigned* sAhi = sm;
    unsigned* sAlo = sm + OFF_ALO;
    const uint32_t smb = smem_u32(sm);

    const int tid = threadIdx.x, lane = tid & 31, wid = tid >> 5;
    const int g = lane >> 2, t = lane & 3;
    const int wm = (wid & 3) * 32, wn = (wid >> 2) * 32;
    const int row0 = blockIdx.x * 128;
    const int NT = nt1 + nt2;

    // ---- stage A once: fp32 -> bf16 hi/lo (coalesced float4 rounds) ----
#pragma unroll
    for (int r = 0; r < 16; r++) {
        int i = r * 256 + tid;          // float4 index within 128x128 tile
        int row = i >> 5, q = i & 31;
        float4 v;
        if (row0 + row < nrows) v = *(const float4*)&A[(size_t)(row0 + row) * HH + q * 4];
        else v = make_float4(0.f, 0.f, 0.f, 0.f);
        unsigned h0 = bf16h(v.x), h1 = bf16h(v.y), h2 = bf16h(v.z), h3 = bf16h(v.w);
        unsigned l0 = bf16h(v.x - bf16f(h0)), l1 = bf16h(v.y - bf16f(h1));
        unsigned l2 = bf16h(v.z - bf16f(h2)), l3 = bf16h(v.w - bf16f(h3));
        int o = row * SAW + q * 2;
        sAhi[o] = h0 | (h1 << 16); sAhi[o + 1] = h2 | (h3 << 16);
        sAlo[o] = l0 | (l1 << 16); sAlo[o + 1] = l2 | (l3 << 16);
    }

    // ldmatrix per-lane address components
    const int a_row_l = ((lane >> 3) & 1) * 8 + (lane & 7);   // row within 16-row frag pair
    const int a_kw_l  = ((lane >> 4) & 1) * 4;                // +4 words for k8-15 matrices
    const int b_row_l = lane & 7;                             // B n within 8 (x2 uses lanes 0-15)
    const int b_kw_l  = ((lane >> 3) & 1) * 4;
    const uint32_t aAddrHi0 = smb + (uint32_t)((wm + a_row_l) * SAW + a_kw_l) * 4;
    const uint32_t aAddrLo0 = aAddrHi0 + (uint32_t)OFF_ALO * 4;
    const uint32_t bAddrBase = (uint32_t)((wn + b_row_l) * SAW + b_kw_l) * 4;

    // B tile staging map: thread -> row tid>>2 (0..63), quarter tid&3 (4 uint4 each)
    const int brow = tid >> 2, bq = tid & 3;
    const uint32_t bdw = (uint32_t)(brow * SAW + bq * 16) * 4;

    auto issueB = [&](int ti) {
        const unsigned short* Bh; const unsigned short* Bl; int col0;
        if (ti < nt1) { Bh = B1h; Bl = B1l; col0 = ti * 64; }
        else          { Bh = B2h; Bl = B2l; col0 = (ti - nt1) * 64; }
        int buf = ti & 1;
        uint32_t dsth = smb + (uint32_t)(OFF_B + buf * 2 * SB) * 4 + bdw;
        uint32_t dstl = dsth + (uint32_t)SB * 4;
        const uint4* srch = (const uint4*)Bh + (size_t)(col0 + brow) * 16 + bq * 4;
        const uint4* srcl = (const uint4*)Bl + (size_t)(col0 + brow) * 16 + bq * 4;
#pragma unroll
        for (int j = 0; j < 4; j++) {
            cpasync16(dsth + j * 16, srch + j);
            cpasync16(dstl + j * 16, srcl + j);
        }
    };

    issueB(0); CP_COMMIT();

    for (int ti = 0; ti < NT; ti++) {
        bool has_next = (ti + 1 < NT);
        if (has_next) { issueB(ti + 1); CP_COMMIT(); }
        if (has_next) CP_WAIT1(); else CP_WAIT0();
        __syncthreads();

        const uint32_t bHiAddr = smb + (uint32_t)(OFF_B + (ti & 1) * 2 * SB) * 4 + bAddrBase;
        const uint32_t bLoAddr = bHiAddr + (uint32_t)SB * 4;

        float acc[2][4][4];
#pragma unroll
        for (int i = 0; i < 2; i++)
#pragma unroll
            for (int j = 0; j < 4; j++)
#pragma unroll
                for (int q = 0; q < 4; q++) acc[i][j][q] = 0.f;

#pragma unroll
        for (int s = 0; s < 8; s++) {
            const uint32_t sOff = (uint32_t)(s * 8) * 4;
            unsigned ahi[2][4], alo[2][4];
#pragma unroll
            for (int ma = 0; ma < 2; ma++) {
                const uint32_t rOff = (uint32_t)(ma * 16 * SAW) * 4;
                ldsm_x4(ahi[ma], aAddrHi0 + rOff + sOff);
                ldsm_x4(alo[ma], aAddrLo0 + rOff + sOff);
            }
#pragma unroll
            for (int na = 0; na < 4; na++) {
                const uint32_t nOff = (uint32_t)(na * 8 * SAW) * 4;
                unsigned bh[2], bl[2];
                ldsm_x2(bh, bHiAddr + nOff + sOff);
                ldsm_x2(bl, bLoAddr + nOff + sOff);
#pragma unroll
                for (int ma = 0; ma < 2; ma++) {
                    mma_bf16(acc[ma][na], ahi[ma], bh[0], bh[1]);
                    mma_bf16(acc[ma][na], ahi[ma], bl[0], bl[1]);
                    mma_bf16(acc[ma][na], alo[ma], bh[0], bh[1]);
                }
            }
        }

        // ---- epilogue for this tile ----
        const float* bias; float* C; int ncols, col0;
        if (ti < nt1) { bias = bias1; C = C1; ncols = ncols1; col0 = ti * 64; }
        else          { bias = bias2; C = C2; ncols = ncols2; col0 = (ti - nt1) * 64; }
#pragma unroll
        for (int ma = 0; ma < 2; ma++) {
#pragma unroll
            for (int na = 0; na < 4; na++) {
                int col = col0 + wn + na * 8 + t * 2;
                float b0 = bias ? bias[col] : 0.f;
                float b1 = bias ? bias[col + 1] : 0.f;
                int r0 = row0 + wm + ma * 16 + g;
                if (r0 < nrows) {
                    float2 o = make_float2(acc[ma][na][0] + b0, acc[ma][na][1] + b1);
                    *(float2*)&C[(size_t)r0 * ncols + col] = o;
                }
                int r1 = r0 + 8;
                if (r1 < nrows) {
                    float2 o = make_float2(acc[ma][na][2] + b0, acc[ma][na][3] + b1);
                    *(float2*)&C[(size_t)r1 * ncols + col] = o;
                }
            }
        }
        __syncthreads();   // protect B buffer reuse before next issue
    }
}

// ---------------- edge gather * weight -> vector red scatter-add ----------------
__global__ __launch_bounds__(256) void edge_scatter_kernel(
    const float* __restrict__ m, const float* __restrict__ ew,
    const int* __restrict__ src, const int* __restrict__ dst,
    float* __restrict__ agg)
{
    long long gid = (long long)blockIdx.x * blockDim.x + threadIdx.x;
    int edge = (int)(gid >> 5);
    int lane = (int)(gid & 31);
    if (edge >= EE) return;

    int s = src[edge];
    int d = dst[edge];
    float w = ew[edge];

    float4 v = *(const float4*)(m + (size_t)s * HH + lane * 4);
    v.x *= w; v.y *= w; v.z *= w; v.w *= w;

    float* dstp = agg + (size_t)d * HH + lane * 4;
    asm volatile("red.global.add.v4.f32 [%0], {%1, %2, %3, %4};"
                 :: "l"(dstp), "f"(v.x), "f"(v.y), "f"(v.z), "f"(v.w)
                 : "memory");
}

// ---------------- GRU elementwise ----------------
__global__ __launch_bounds__(256) void gru_elem_kernel(
    const float* __restrict__ gi, const float* __restrict__ gh,
    const float* __restrict__ x, float* __restrict__ xout, int n4)
{
    int idx = blockIdx.x * blockDim.x + threadIdx.x;
    if (idx >= n4) return;
    int node = idx >> 5;
    int c4   = idx & 31;

    const float4* gi4 = (const float4*)gi;
    const float4* gh4 = (const float4*)gh;
    size_t base = (size_t)node * 96 + c4;

    float4 ir = gi4[base];
    float4 iz = gi4[base + 32];
    float4 in_ = gi4[base + 64];
    float4 hr = gh4[base];
    float4 hz = gh4[base + 32];
    float4 hn = gh4[base + 64];
    float4 xv = ((const float4*)x)[idx];

    float4 o;
    {
        float r  = 1.f / (1.f + __expf(-(ir.x + hr.x)));
        float zg = 1.f / (1.f + __expf(-(iz.x + hz.x)));
        float nn = tanhf(in_.x + r * hn.x);
        o.x = (1.f - zg) * nn + zg * xv.x;
    }
    {
        float r  = 1.f / (1.f + __expf(-(ir.y + hr.y)));
        float zg = 1.f / (1.f + __expf(-(iz.y + hz.y)));
        float nn = tanhf(in_.y + r * hn.y);
        o.y = (1.f - zg) * nn + zg * xv.y;
    }
    {
        float r  = 1.f / (1.f + __expf(-(ir.z + hr.z)));
        float zg = 1.f / (1.f + __expf(-(iz.z + hz.z)));
        float nn = tanhf(in_.z + r * hn.z);
        o.z = (1.f - zg) * nn + zg * xv.z;
    }
    {
        float r  = 1.f / (1.f + __expf(-(ir.w + hr.w)));
        float zg = 1.f / (1.f + __expf(-(iz.w + hz.w)));
        float nn = tanhf(in_.w + r * hn.w);
        o.w = (1.f - zg) * nn + zg * xv.w;
    }
    ((float4*)xout)[idx] = o;
}

// ---------------- host ----------------
extern "C" void kernel_launch(void* const* d_in, const int* in_sizes, int n_in,
                              void* d_out, int out_size)
{
    const float* z = nullptr; const float* ew = nullptr; const void* ei = nullptr;
    const float* mats[3] = {nullptr, nullptr, nullptr}; int nmat = 0;
    const float* vecs[2] = {nullptr, nullptr};          int nvec = 0;
    for (int i = 0; i < n_in; i++) {
        int sz = in_sizes[i];
        if      (sz == NN * HH)      z  = (const float*)d_in[i];
        else if (sz == EE)           ew = (const float*)d_in[i];
        else if (sz == 2 * EE)       ei = d_in[i];
        else if (sz == 3 * HH * HH) { if (nmat < 3) mats[nmat++] = (const float*)d_in[i]; }
        else if (sz == 3 * HH)      { if (nvec < 2) vecs[nvec++] = (const float*)d_in[i]; }
    }
    if (!z  && n_in > 0) z  = (const float*)d_in[0];
    if (!ew && n_in > 1) ew = (const float*)d_in[1];
    if (nmat < 3) { mats[0] = (const float*)d_in[2]; mats[1] = (const float*)d_in[3]; mats[2] = (const float*)d_in[4]; }
    if (nvec < 2) { vecs[0] = (const float*)d_in[5]; vecs[1] = (const float*)d_in[6]; }
    if (!ei && n_in > 7) ei = d_in[7];

    const float* weight = mats[0];
    const float* w_ih   = mats[1];
    const float* w_hh   = mats[2];
    const float* b_ih   = vecs[0];
    const float* b_hh   = vecs[1];
    float*       out    = (float*)d_out;

    float *pm, *pagg, *pgi, *pgh, *px;
    unsigned short *pB1h, *pB1l, *pIhh, *pIhl, *pHhh, *pHhl;
    int *psrc, *pdst;
    cudaGetSymbolAddress((void**)&pm,   g_m);
    cudaGetSymbolAddress((void**)&pagg, g_agg);
    cudaGetSymbolAddress((void**)&pgi,  g_gi);
    cudaGetSymbolAddress((void**)&pgh,  g_gh);
    cudaGetSymbolAddress((void**)&px,   g_x);
    cudaGetSymbolAddress((void**)&pB1h, g_B1hi);
    cudaGetSymbolAddress((void**)&pB1l, g_B1lo);
    cudaGetSymbolAddress((void**)&pIhh, g_Bihhi);
    cudaGetSymbolAddress((void**)&pIhl, g_Bihlo);
    cudaGetSymbolAddress((void**)&pHhh, g_Bhhhi);
    cudaGetSymbolAddress((void**)&pHhl, g_Bhhlo);
    cudaGetSymbolAddress((void**)&psrc, g_src);
    cudaGetSymbolAddress((void**)&pdst, g_dst);

    static int smem_set = 0;
    if (!smem_set) {
        cudaFuncSetAttribute(mma_gemm_persist, cudaFuncAttributeMaxDynamicSharedMemorySize, SMEM_BYTES);
        smem_set = 1;
    }

    const int GMX = (NN + 127) / 128;                 // 782
    const int n4  = NN * (HH / 4);
    const int zgrid = (n4 + 255) / 256;
    const long long ethreads = (long long)EE * 32;
    const int egrid = (int)((ethreads + 255) / 256);

    // launches 1-4 (keeps the big GEMM at launch slot 5 for ncu's fixed skip)
    detect_idx_kernel<<<1, 256>>>((const int*)ei);
    prep_idx_kernel<<<(EE + 255) / 256, 256>>>(ei, psrc, pdst);
    split_w1_kernel<<<(3 * HH * HH + 255) / 256, 256>>>(weight, pB1h, pB1l);
    split_w2_kernel<<<(2 * H3 * HH + 255) / 256, 256>>>(w_ih, w_hh, pIhh, pIhl, pHhh, pHhl);

    const float* x = z;
    for (int l = 0; l < LL; l++) {
        // fused: m = x@W[l] (2 tiles) and gh = x@w_hh^T + b_hh (6 tiles); A staged once
        mma_gemm_persist<<<GMX, 256, SMEM_BYTES>>>(
            x, NN,
            pB1h + (size_t)l * HH * HH, pB1l + (size_t)l * HH * HH, nullptr, pm, HH, 2,
            pHhh, pHhl, b_hh, pgh, H3, 6);
        // agg = segment_sum(m[src] * ew, dst)
        zero_kernel<<<zgrid, 256>>>((float4*)pagg, n4);
        edge_scatter_kernel<<<egrid, 256>>>(pm, ew, psrc, pdst, pagg);
        // gi = agg @ w_ih^T + b_ih (6 tiles)
        mma_gemm_persist<<<GMX, 256, SMEM_BYTES>>>(
            pagg, NN,
            pIhh, pIhl, b_ih, pgi, H3, 6,
            nullptr, nullptr, nullptr, nullptr, 0, 0);
        // GRU elementwise
        float* xout = (l == LL - 1) ? out : px;
        gru_elem_kernel<<<zgrid, 256>>>(pgi, pgh, x, xout, n4);
        x = px;
    }
}

// round 15
// speedup vs baseline: 1.0985x; 1.0985x over previous
#include <cuda_runtime.h>
#include <cstdint>

#define NN 100000
#define EE 1600000
#define HH 128
#define H3 384
#define LL 3

// ---------------- scratch (static device globals; no allocation) ----------------
__device__ __align__(256) float g_m[(size_t)NN * HH];     // m = x @ W[l]
__device__ __align__(256) float g_agg[(size_t)NN * HH];   // aggregated messages
__device__ __align__(256) float g_gh[(size_t)NN * H3];    // x @ w_hh^T + b_hh
__device__ __align__(256) float g_x[(size_t)NN * HH];     // hidden state ping buffer
__device__ int g_idx64;
__device__ __align__(256) int g_src[EE];
__device__ __align__(256) int g_dst[EE];
// CSR by destination
__device__ __align__(256) int g_deg[NN];
__device__ __align__(256) int g_off[NN + 1];
__device__ __align__(256) int g_cur[NN];
__device__ __align__(256) int g_esrc[EE];
__device__ __align__(256) float g_esw[EE];

// bf16 hi/lo split weights, stored [n][k] (k contiguous, K=128)
__device__ __align__(256) unsigned short g_B1hi[3 * HH * HH];
__device__ __align__(256) unsigned short g_B1lo[3 * HH * HH];
__device__ __align__(256) unsigned short g_Bihhi[H3 * HH];
__device__ __align__(256) unsigned short g_Bihlo[H3 * HH];
__device__ __align__(256) unsigned short g_Bhhhi[H3 * HH];
__device__ __align__(256) unsigned short g_Bhhlo[H3 * HH];

// ---------------- bf16 split helpers ----------------
__device__ __forceinline__ unsigned bf16h(float f) {
    unsigned x = __float_as_uint(f);
    return (x + 0x7fffu + ((x >> 16) & 1u)) >> 16;   // rn-even to bf16 bits
}
__device__ __forceinline__ float bf16f(unsigned b) { return __uint_as_float(b << 16); }

__device__ __forceinline__ uint32_t smem_u32(const void* p) {
    uint32_t a;
    asm("{ .reg .u64 t; cvta.to.shared.u64 t, %1; cvt.u32.u64 %0, t; }" : "=r"(a) : "l"(p));
    return a;
}
__device__ __forceinline__ void cpasync16(uint32_t dst, const void* src) {
    asm volatile("cp.async.cg.shared.global [%0], [%1], 16;" :: "r"(dst), "l"(src));
}
#define CP_COMMIT() asm volatile("cp.async.commit_group;" ::: "memory")
#define CP_WAIT1()  asm volatile("cp.async.wait_group 1;" ::: "memory")
#define CP_WAIT0()  asm volatile("cp.async.wait_group 0;" ::: "memory")

__device__ __forceinline__ void ldsm_x4(unsigned* r, uint32_t addr) {
    asm volatile("ldmatrix.sync.aligned.m8n8.x4.shared.b16 {%0,%1,%2,%3}, [%4];"
        : "=r"(r[0]), "=r"(r[1]), "=r"(r[2]), "=r"(r[3]) : "r"(addr));
}
__device__ __forceinline__ void ldsm_x2(unsigned* r, uint32_t addr) {
    asm volatile("ldmatrix.sync.aligned.m8n8.x2.shared.b16 {%0,%1}, [%2];"
        : "=r"(r[0]), "=r"(r[1]) : "r"(addr));
}

// ---------------- detect edge_index dtype ----------------
__global__ void detect_idx_kernel(const int* __restrict__ ei32) {
    int bad = 0;
    for (int i = threadIdx.x; i < 4096; i += blockDim.x)
        if ((i & 1) && ei32[i] != 0) bad = 1;
    bad = __syncthreads_or(bad);
    if (threadIdx.x == 0) g_idx64 = bad ? 0 : 1;
}

// ---------------- zero degree array ----------------
__global__ void zero_deg_kernel() {
    int i = blockIdx.x * blockDim.x + threadIdx.x;
    if (i < NN) g_deg[i] = 0;
}

// ---------------- decode edge_index -> int32 src/dst + dst histogram ----------------
__global__ __launch_bounds__(256) void prep_idx_kernel(const void* __restrict__ ei) {
    int e = blockIdx.x * blockDim.x + threadIdx.x;
    if (e >= EE) return;
    int s, d;
    if (g_idx64) {
        const long long* p = (const long long*)ei;
        s = (int)p[e]; d = (int)p[EE + e];
    } else {
        const int* p = (const int*)ei;
        s = p[e]; d = p[EE + e];
    }
    if ((unsigned)s >= NN) s = 0;
    if ((unsigned)d >= NN) d = 0;
    g_src[e] = s; g_dst[e] = d;
    atomicAdd(&g_deg[d], 1);
}

// ---------------- exclusive scan of g_deg (single block) ----------------
__global__ __launch_bounds__(1024) void scan_kernel() {
    __shared__ int sdata[1024];
    __shared__ int carry;
    if (threadIdx.x == 0) carry = 0;
    __syncthreads();
    for (int base = 0; base < NN; base += 1024) {
        int i = base + threadIdx.x;
        int v = (i < NN) ? g_deg[i] : 0;
        sdata[threadIdx.x] = v;
        __syncthreads();
        for (int off = 1; off < 1024; off <<= 1) {
            int t = (threadIdx.x >= off) ? sdata[threadIdx.x - off] : 0;
            __syncthreads();
            sdata[threadIdx.x] += t;
            __syncthreads();
        }
        int incl = sdata[threadIdx.x];
        int total = sdata[1023];
        int excl = incl - v + carry;
        if (i < NN) { g_off[i] = excl; g_cur[i] = excl; }
        __syncthreads();
        if (threadIdx.x == 0) carry += total;
        __syncthreads();
    }
    if (threadIdx.x == 0) g_off[NN] = carry;
}

// ---------------- reorder edges by dst ----------------
__global__ __launch_bounds__(256) void reorder_kernel(const float* __restrict__ ew) {
    int e = blockIdx.x * blockDim.x + threadIdx.x;
    if (e >= EE) return;
    int d = g_dst[e];
    int pos = atomicAdd(&g_cur[d], 1);
    g_esrc[pos] = g_src[e];
    g_esw[pos]  = ew[e];
}

// ---------------- split weight[l] ([k][n]) -> transposed [n][k] hi/lo ----------------
__global__ void split_w1_kernel(const float* __restrict__ w,
                                unsigned short* __restrict__ hi,
                                unsigned short* __restrict__ lo) {
    int i = blockIdx.x * blockDim.x + threadIdx.x;
    if (i >= 3 * HH * HH) return;
    int l = i >> 14, rem = i & 16383;
    int k = rem >> 7, n = rem & 127;
    float f = w[i];
    unsigned h = bf16h(f);
    unsigned lb = bf16h(f - bf16f(h));
    int o = l * HH * HH + n * HH + k;
    hi[o] = (unsigned short)h;
    lo[o] = (unsigned short)lb;
}

// ---------------- split BOTH gru weight matrices in one launch ----------------
__global__ void split_w2_kernel(const float* __restrict__ wa, const float* __restrict__ wb,
                                unsigned short* __restrict__ hia, unsigned short* __restrict__ loa,
                                unsigned short* __restrict__ hib, unsigned short* __restrict__ lob) {
    int i = blockIdx.x * blockDim.x + threadIdx.x;
    int count = H3 * HH;
    if (i < count) {
        float f = wa[i];
        unsigned h = bf16h(f);
        hia[i] = (unsigned short)h;
        loa[i] = (unsigned short)bf16h(f - bf16f(h));
    } else if (i < 2 * count) {
        int j = i - count;
        float f = wb[j];
        unsigned h = bf16h(f);
        hib[j] = (unsigned short)h;
        lob[j] = (unsigned short)bf16h(f - bf16f(h));
    }
}

// ---------------- shared GEMM pieces ----------------
#define SAW 68
#define SA  (128 * SAW)
#define SB  (64 * SAW)
#define OFF_ALO SA
#define OFF_B   (2 * SA)
#define SMEM_WORDS (2 * SA + 4 * SB)
#define SMEM_BYTES (SMEM_WORDS * 4)  // 139264

__device__ __forceinline__ void mma_bf16(float* c, const unsigned* a, unsigned b0, unsigned b1) {
    asm volatile(
        "mma.sync.aligned.m16n8k16.row.col.f32.bf16.bf16.f32 "
        "{%0,%1,%2,%3}, {%4,%5,%6,%7}, {%8,%9}, {%0,%1,%2,%3};"
        : "+f"(c[0]), "+f"(c[1]), "+f"(c[2]), "+f"(c[3])
        : "r"(a[0]), "r"(a[1]), "r"(a[2]), "r"(a[3]), "r"(b0), "r"(b1));
}

// stage 128x128 fp32 A tile into smem as bf16 hi/lo
__device__ __forceinline__ void stage_A(const float* __restrict__ A, int nrows, int row0,
                                        unsigned* sAhi, unsigned* sAlo, int tid) {
#pragma unroll
    for (int r = 0; r < 16; r++) {
        int i = r * 256 + tid;
        int row = i >> 5, q = i & 31;
        float4 v;
        if (row0 + row < nrows) v = *(const float4*)&A[(size_t)(row0 + row) * HH + q * 4];
        else v = make_float4(0.f, 0.f, 0.f, 0.f);
        unsigned h0 = bf16h(v.x), h1 = bf16h(v.y), h2 = bf16h(v.z), h3 = bf16h(v.w);
        unsigned l0 = bf16h(v.x - bf16f(h0)), l1 = bf16h(v.y - bf16f(h1));
        unsigned l2 = bf16h(v.z - bf16f(h2)), l3 = bf16h(v.w - bf16f(h3));
        int o = row * SAW + q * 2;
        sAhi[o] = h0 | (h1 << 16); sAhi[o + 1] = h2 | (h3 << 16);
        sAlo[o] = l0 | (l1 << 16); sAlo[o + 1] = l2 | (l3 << 16);
    }
}

// compute one 128x64 tile: 8 k-steps, 3-term split
#define TILE_COMPUTE(accv, bHiAddr, bLoAddr)                                       \
    {                                                                              \
        _Pragma("unroll")                                                          \
        for (int s = 0; s < 8; s++) {                                              \
            const uint32_t sOff = (uint32_t)(s * 8) * 4;                           \
            unsigned ahi[2][4], alo[2][4];                                         \
            _Pragma("unroll")                                                      \
            for (int ma = 0; ma < 2; ma++) {                                       \
                const uint32_t rOff = (uint32_t)(ma * 16 * SAW) * 4;               \
                ldsm_x4(ahi[ma], aAddrHi0 + rOff + sOff);                          \
                ldsm_x4(alo[ma], aAddrLo0 + rOff + sOff);                          \
            }                                                                      \
            _Pragma("unroll")                                                      \
            for (int na = 0; na < 4; na++) {                                       \
                const uint32_t nOff = (uint32_t)(na * 8 * SAW) * 4;                \
                unsigned bh[2], bl[2];                                             \
                ldsm_x2(bh, (bHiAddr) + nOff + sOff);                              \
                ldsm_x2(bl, (bLoAddr) + nOff + sOff);                              \
                _Pragma("unroll")                                                  \
                for (int ma = 0; ma < 2; ma++) {                                   \
                    mma_bf16(accv[ma][na], ahi[ma], bh[0], bh[1]);                 \
                    mma_bf16(accv[ma][na], ahi[ma], bl[0], bl[1]);                 \
                    mma_bf16(accv[ma][na], alo[ma], bh[0], bh[1]);                 \
                }                                                                  \
            }                                                                      \
        }                                                                          \
    }

// ---------------- persistent-A GEMM, dual output sets (m + gh) ----------------
__global__ __launch_bounds__(256) void mma_gemm_persist(
    const float* __restrict__ A, int nrows,
    const unsigned short* __restrict__ B1h, const unsigned short* __restrict__ B1l,
    const float* __restrict__ bias1, float* __restrict__ C1, int ncols1, int nt1,
    const unsigned short* __restrict__ B2h, const unsigned short* __restrict__ B2l,
    const float* __restrict__ bias2, float* __restrict__ C2, int ncols2, int nt2)
{
    extern __shared__ __align__(16) unsigned sm[];
    unsigned* sAhi = sm;
    unsigned* sAlo = sm + OFF_ALO;
    const uint32_t smb = smem_u32(sm);

    const int tid = threadIdx.x, lane = tid & 31, wid = tid >> 5;
    const int lg = lane >> 2, t = lane & 3;
    const int wm = (wid & 3) * 32, wn = (wid >> 2) * 32;
    const int row0 = blockIdx.x * 128;
    const int NT = nt1 + nt2;

    stage_A(A, nrows, row0, sAhi, sAlo, tid);

    const int a_row_l = ((lane >> 3) & 1) * 8 + (lane & 7);
    const int a_kw_l  = ((lane >> 4) & 1) * 4;
    const int b_row_l = lane & 7;
    const int b_kw_l  = ((lane >> 3) & 1) * 4;
    const uint32_t aAddrHi0 = smb + (uint32_t)((wm + a_row_l) * SAW + a_kw_l) * 4;
    const uint32_t aAddrLo0 = aAddrHi0 + (uint32_t)OFF_ALO * 4;
    const uint32_t bAddrBase = (uint32_t)((wn + b_row_l) * SAW + b_kw_l) * 4;

    const int brow = tid >> 2, bq = tid & 3;
    const uint32_t bdw = (uint32_t)(brow * SAW + bq * 16) * 4;

    auto issueB = [&](int ti) {
        const unsigned short* Bh; const unsigned short* Bl; int col0;
        if (ti < nt1) { Bh = B1h; Bl = B1l; col0 = ti * 64; }
        else          { Bh = B2h; Bl = B2l; col0 = (ti - nt1) * 64; }
        int buf = ti & 1;
        uint32_t dsth = smb + (uint32_t)(OFF_B + buf * 2 * SB) * 4 + bdw;
        uint32_t dstl = dsth + (uint32_t)SB * 4;
        const uint4* srch = (const uint4*)Bh + (size_t)(col0 + brow) * 16 + bq * 4;
        const uint4* srcl = (const uint4*)Bl + (size_t)(col0 + brow) * 16 + bq * 4;
#pragma unroll
        for (int j = 0; j < 4; j++) {
            cpasync16(dsth + j * 16, srch + j);
            cpasync16(dstl + j * 16, srcl + j);
        }
    };

    issueB(0); CP_COMMIT();

    for (int ti = 0; ti < NT; ti++) {
        bool has_next = (ti + 1 < NT);
        if (has_next) { issueB(ti + 1); CP_COMMIT(); }
        if (has_next) CP_WAIT1(); else CP_WAIT0();
        __syncthreads();

        const uint32_t bHiAddr = smb + (uint32_t)(OFF_B + (ti & 1) * 2 * SB) * 4 + bAddrBase;
        const uint32_t bLoAddr = bHiAddr + (uint32_t)SB * 4;

        float acc[2][4][4];
#pragma unroll
        for (int i = 0; i < 2; i++)
#pragma unroll
            for (int j = 0; j < 4; j++)
#pragma unroll
                for (int q = 0; q < 4; q++) acc[i][j][q] = 0.f;

        TILE_COMPUTE(acc, bHiAddr, bLoAddr);

        const float* bias; float* C; int ncols, col0;
        if (ti < nt1) { bias = bias1; C = C1; ncols = ncols1; col0 = ti * 64; }
        else          { bias = bias2; C = C2; ncols = ncols2; col0 = (ti - nt1) * 64; }
#pragma unroll
        for (int ma = 0; ma < 2; ma++) {
#pragma unroll
            for (int na = 0; na < 4; na++) {
                int col = col0 + wn + na * 8 + t * 2;
                float b0 = bias ? bias[col] : 0.f;
                float b1 = bias ? bias[col + 1] : 0.f;
                int r0 = row0 + wm + ma * 16 + lg;
                if (r0 < nrows) {
                    float2 o = make_float2(acc[ma][na][0] + b0, acc[ma][na][1] + b1);
                    *(float2*)&C[(size_t)r0 * ncols + col] = o;
                }
                int r1 = r0 + 8;
                if (r1 < nrows) {
                    float2 o = make_float2(acc[ma][na][2] + b0, acc[ma][na][3] + b1);
                    *(float2*)&C[(size_t)r1 * ncols + col] = o;
                }
            }
        }
        __syncthreads();
    }
}

// ---------------- persistent-A GEMM with fused GRU (gi = A@w_ih^T + b_ih) ----------
// Tile order (r,z,n | r,z,n): col offsets (0,128,256),(64,192,320). After each
// group of 3, apply GRU gates in-register and write xout; gi never hits global.
__global__ __launch_bounds__(256) void mma_gemm_gru(
    const float* __restrict__ A, int nrows,
    const unsigned short* __restrict__ Bh16, const unsigned short* __restrict__ Bl16,
    const float* __restrict__ bias,
    const float* __restrict__ gh, const float* __restrict__ x, float* __restrict__ xout)
{
    extern __shared__ __align__(16) unsigned sm[];
    unsigned* sAhi = sm;
    unsigned* sAlo = sm + OFF_ALO;
    const uint32_t smb = smem_u32(sm);

    const int tid = threadIdx.x, lane = tid & 31, wid = tid >> 5;
    const int lg = lane >> 2, t = lane & 3;
    const int wm = (wid & 3) * 32, wn = (wid >> 2) * 32;
    const int row0 = blockIdx.x * 128;

    stage_A(A, nrows, row0, sAhi, sAlo, tid);

    const int a_row_l = ((lane >> 3) & 1) * 8 + (lane & 7);
    const int a_kw_l  = ((lane >> 4) & 1) * 4;
    const int b_row_l = lane & 7;
    const int b_kw_l  = ((lane >> 3) & 1) * 4;
    const uint32_t aAddrHi0 = smb + (uint32_t)((wm + a_row_l) * SAW + a_kw_l) * 4;
    const uint32_t aAddrLo0 = aAddrHi0 + (uint32_t)OFF_ALO * 4;
    const uint32_t bAddrBase = (uint32_t)((wn + b_row_l) * SAW + b_kw_l) * 4;

    const int brow = tid >> 2, bq = tid & 3;
    const uint32_t bdw = (uint32_t)(brow * SAW + bq * 16) * 4;

    // tile s (0..5) -> gi column offset
    auto tileCol = [](int s) { return (s % 3) * 128 + (s / 3) * 64; };

    auto issueB = [&](int s) {
        int col0 = tileCol(s);
        int buf = s & 1;
        uint32_t dsth = smb + (uint32_t)(OFF_B + buf * 2 * SB) * 4 + bdw;
        uint32_t dstl = dsth + (uint32_t)SB * 4;
        const uint4* srch = (const uint4*)Bh16 + (size_t)(col0 + brow) * 16 + bq * 4;
        const uint4* srcl = (const uint4*)Bl16 + (size_t)(col0 + brow) * 16 + bq * 4;
#pragma unroll
        for (int j = 0; j < 4; j++) {
            cpasync16(dsth + j * 16, srch + j);
            cpasync16(dstl + j * 16, srcl + j);
        }
    };

    issueB(0); CP_COMMIT();

    float acc[3][2][4][4];   // r, z, n accumulators for current group

    for (int group = 0; group < 2; group++) {
#pragma unroll
        for (int part = 0; part < 3; part++) {
            int s = group * 3 + part;
            bool has_next = (s + 1 < 6);
            if (has_next) { issueB(s + 1); CP_COMMIT(); }
            if (has_next) CP_WAIT1(); else CP_WAIT0();
            __syncthreads();

            const uint32_t bHiAddr = smb + (uint32_t)(OFF_B + (s & 1) * 2 * SB) * 4 + bAddrBase;
            const uint32_t bLoAddr = bHiAddr + (uint32_t)SB * 4;

#pragma unroll
            for (int i = 0; i < 2; i++)
#pragma unroll
                for (int j = 0; j < 4; j++)
#pragma unroll
                    for (int q = 0; q < 4; q++) acc[part][i][j][q] = 0.f;

            TILE_COMPUTE(acc[part], bHiAddr, bLoAddr);
            __syncthreads();
        }

        // ---- fused GRU epilogue for feature cols [group*64, group*64+64) ----
#pragma unroll
        for (int ma = 0; ma < 2; ma++) {
#pragma unroll
            for (int na = 0; na < 4; na++) {
                int col = group * 64 + wn + na * 8 + t * 2;     // 0..127
                float bR0 = bias[col],       bR1 = bias[col + 1];
                float bZ0 = bias[col + 128], bZ1 = bias[col + 129];
                float bN0 = bias[col + 256], bN1 = bias[col + 257];
#pragma unroll
                for (int half = 0; half < 2; half++) {
                    int row = row0 + wm + ma * 16 + lg + half * 8;
                    if (row >= nrows) continue;
                    int q0 = half * 2;
                    float giR0 = acc[0][ma][na][q0]     + bR0;
                    float giR1 = acc[0][ma][na][q0 + 1] + bR1;
                    float giZ0 = acc[1][ma][na][q0]     + bZ0;
                    float giZ1 = acc[1][ma][na][q0 + 1] + bZ1;
                    float giN0 = acc[2][ma][na][q0]     + bN0;
                    float giN1 = acc[2][ma][na][q0 + 1] + bN1;
                    const float* ghrow = gh + (size_t)row * H3;
                    float2 ghR = *(const float2*)&ghrow[col];
                    float2 ghZ = *(const float2*)&ghrow[col + 128];
                    float2 ghN = *(const float2*)&ghrow[col + 256];
                    float2 xv  = *(const float2*)&x[(size_t)row * HH + col];
                    float r0 = 1.f / (1.f + __expf(-(giR0 + ghR.x)));
                    float r1 = 1.f / (1.f + __expf(-(giR1 + ghR.y)));
                    float z0 = 1.f / (1.f + __expf(-(giZ0 + ghZ.x)));
                    float z1 = 1.f / (1.f + __expf(-(giZ1 + ghZ.y)));
                    float n0 = tanhf(giN0 + r0 * ghN.x);
                    float n1 = tanhf(giN1 + r1 * ghN.y);
                    float2 o = make_float2((1.f - z0) * n0 + z0 * xv.x,
                                           (1.f - z1) * n1 + z1 * xv.y);
                    *(float2*)&xout[(size_t)row * HH + col] = o;
                }
            }
        }
    }
}

// ---------------- CSR aggregate: warp per destination node ----------------
__global__ __launch_bounds__(256) void csr_agg_kernel(
    const float* __restrict__ m, float* __restrict__ agg)
{
    int warp = (int)((blockIdx.x * blockDim.x + threadIdx.x) >> 5);
    int lane = threadIdx.x & 31;
    if (warp >= NN) return;
    int e = g_off[warp], end = g_off[warp + 1];
    float4 acc = make_float4(0.f, 0.f, 0.f, 0.f);
    for (; e < end; e++) {
        int s = g_esrc[e];
        float w = g_esw[e];
        float4 v = *(const float4*)(m + (size_t)s * HH + lane * 4);
        acc.x += v.x * w; acc.y += v.y * w; acc.z += v.z * w; acc.w += v.w * w;
    }
    *(float4*)(agg + (size_t)warp * HH + lane * 4) = acc;
}

// ---------------- host ----------------
extern "C" void kernel_launch(void* const* d_in, const int* in_sizes, int n_in,
                              void* d_out, int out_size)
{
    const float* z = nullptr; const float* ew = nullptr; const void* ei = nullptr;
    const float* mats[3] = {nullptr, nullptr, nullptr}; int nmat = 0;
    const float* vecs[2] = {nullptr, nullptr};          int nvec = 0;
    for (int i = 0; i < n_in; i++) {
        int sz = in_sizes[i];
        if      (sz == NN * HH)      z  = (const float*)d_in[i];
        else if (sz == EE)           ew = (const float*)d_in[i];
        else if (sz == 2 * EE)       ei = d_in[i];
        else if (sz == 3 * HH * HH) { if (nmat < 3) mats[nmat++] = (const float*)d_in[i]; }
        else if (sz == 3 * HH)      { if (nvec < 2) vecs[nvec++] = (const float*)d_in[i]; }
    }
    if (!z  && n_in > 0) z  = (const float*)d_in[0];
    if (!ew && n_in > 1) ew = (const float*)d_in[1];
    if (nmat < 3) { mats[0] = (const float*)d_in[2]; mats[1] = (const float*)d_in[3]; mats[2] = (const float*)d_in[4]; }
    if (nvec < 2) { vecs[0] = (const float*)d_in[5]; vecs[1] = (const float*)d_in[6]; }
    if (!ei && n_in > 7) ei = d_in[7];

    const float* weight = mats[0];
    const float* w_ih   = mats[1];
    const float* w_hh   = mats[2];
    const float* b_ih   = vecs[0];
    const float* b_hh   = vecs[1];
    float*       out    = (float*)d_out;

    float *pm, *pagg, *pgh, *px;
    unsigned short *pB1h, *pB1l, *pIhh, *pIhl, *pHhh, *pHhl;
    cudaGetSymbolAddress((void**)&pm,   g_m);
    cudaGetSymbolAddress((void**)&pagg, g_agg);
    cudaGetSymbolAddress((void**)&pgh,  g_gh);
    cudaGetSymbolAddress((void**)&px,   g_x);
    cudaGetSymbolAddress((void**)&pB1h, g_B1hi);
    cudaGetSymbolAddress((void**)&pB1l, g_B1lo);
    cudaGetSymbolAddress((void**)&pIhh, g_Bihhi);
    cudaGetSymbolAddress((void**)&pIhl, g_Bihlo);
    cudaGetSymbolAddress((void**)&pHhh, g_Bhhhi);
    cudaGetSymbolAddress((void**)&pHhl, g_Bhhlo);

    static int smem_set = 0;
    if (!smem_set) {
        cudaFuncSetAttribute(mma_gemm_persist, cudaFuncAttributeMaxDynamicSharedMemorySize, SMEM_BYTES);
        cudaFuncSetAttribute(mma_gemm_gru,     cudaFuncAttributeMaxDynamicSharedMemorySize, SMEM_BYTES);
        smem_set = 1;
    }

    const int GMX = (NN + 127) / 128;                 // 782
    const int aggGrid = (NN * 32 + 255) / 256;        // warp per dst

    detect_idx_kernel<<<1, 256>>>((const int*)ei);
    zero_deg_kernel<<<(NN + 255) / 256, 256>>>();
    prep_idx_kernel<<<(EE + 255) / 256, 256>>>(ei);
    scan_kernel<<<1, 1024>>>();
    reorder_kernel<<<(EE + 255) / 256, 256>>>(ew);
    split_w1_kernel<<<(3 * HH * HH + 255) / 256, 256>>>(weight, pB1h, pB1l);
    split_w2_kernel<<<(2 * H3 * HH + 255) / 256, 256>>>(w_ih, w_hh, pIhh, pIhl, pHhh, pHhl);

    const float* x = z;
    for (int l = 0; l < LL; l++) {
        // fused: m = x@W[l] (2 tiles) and gh = x@w_hh^T + b_hh (6 tiles); A staged once
        mma_gemm_persist<<<GMX, 256, SMEM_BYTES>>>(
            x, NN,
            pB1h + (size_t)l * HH * HH, pB1l + (size_t)l * HH * HH, nullptr, pm, HH, 2,
            pHhh, pHhl, b_hh, pgh, H3, 6);
        // agg = segment_sum(m[src] * ew, dst)  — CSR, no atomics, no zeroing
        csr_agg_kernel<<<aggGrid, 256>>>(pm, pagg);
        // gi GEMM + fused GRU -> next x
        float* xout = (l == LL - 1) ? out : px;
        mma_gemm_gru<<<GMX, 256, SMEM_BYTES>>>(
            pagg, NN, pIhh, pIhl, b_ih, pgh, x, xout);
        x = px;
    }
}

// round 16
// speedup vs baseline: 1.1952x; 1.0880x over previous
#include <cuda_runtime.h>
#include <cstdint>

#define NN 100000
#define EE 1600000
#define HH 128
#define H3 384
#define LL 3

// ---------------- scratch (static device globals; no allocation) ----------------
__device__ __align__(256) float g_m[(size_t)NN * HH];     // m = x @ W[l]
__device__ __align__(256) float g_agg[(size_t)NN * HH];   // aggregated messages
__device__ __align__(256) float g_gh[(size_t)NN * H3];    // x @ w_hh^T + b_hh
__device__ __align__(256) float g_x[(size_t)NN * HH];     // hidden state ping buffer
__device__ int g_idx64;
__device__ __align__(256) int g_src[EE];
__device__ __align__(256) int g_dst[EE];
// CSR by destination
__device__ __align__(256) int g_deg[NN];
__device__ __align__(256) int g_off[NN + 1];
__device__ __align__(256) int g_cur[NN];
__device__ __align__(256) int g_bsum[128];
__device__ __align__(256) int g_boff[128];
__device__ __align__(256) int g_esrc[EE];
__device__ __align__(256) float g_esw[EE];

// bf16 hi/lo split weights, stored [n][k] (k contiguous, K=128)
__device__ __align__(256) unsigned short g_B1hi[3 * HH * HH];
__device__ __align__(256) unsigned short g_B1lo[3 * HH * HH];
__device__ __align__(256) unsigned short g_Bihhi[H3 * HH];
__device__ __align__(256) unsigned short g_Bihlo[H3 * HH];
__device__ __align__(256) unsigned short g_Bhhhi[H3 * HH];
__device__ __align__(256) unsigned short g_Bhhlo[H3 * HH];

// ---------------- bf16 split helpers ----------------
__device__ __forceinline__ unsigned bf16h(float f) {
    unsigned x = __float_as_uint(f);
    return (x + 0x7fffu + ((x >> 16) & 1u)) >> 16;   // rn-even to bf16 bits
}
__device__ __forceinline__ float bf16f(unsigned b) { return __uint_as_float(b << 16); }

__device__ __forceinline__ uint32_t smem_u32(const void* p) {
    uint32_t a;
    asm("{ .reg .u64 t; cvta.to.shared.u64 t, %1; cvt.u32.u64 %0, t; }" : "=r"(a) : "l"(p));
    return a;
}
__device__ __forceinline__ void cpasync16(uint32_t dst, const void* src) {
    asm volatile("cp.async.cg.shared.global [%0], [%1], 16;" :: "r"(dst), "l"(src));
}
#define CP_COMMIT() asm volatile("cp.async.commit_group;" ::: "memory")
#define CP_WAIT1()  asm volatile("cp.async.wait_group 1;" ::: "memory")
#define CP_WAIT0()  asm volatile("cp.async.wait_group 0;" ::: "memory")

__device__ __forceinline__ void ldsm_x4(unsigned* r, uint32_t addr) {
    asm volatile("ldmatrix.sync.aligned.m8n8.x4.shared.b16 {%0,%1,%2,%3}, [%4];"
        : "=r"(r[0]), "=r"(r[1]), "=r"(r[2]), "=r"(r[3]) : "r"(addr));
}
__device__ __forceinline__ void ldsm_x2(unsigned* r, uint32_t addr) {
    asm volatile("ldmatrix.sync.aligned.m8n8.x2.shared.b16 {%0,%1}, [%2];"
        : "=r"(r[0]), "=r"(r[1]) : "r"(addr));
}

// ---------------- detect edge_index dtype ----------------
__global__ void detect_idx_kernel(const int* __restrict__ ei32) {
    int bad = 0;
    for (int i = threadIdx.x; i < 4096; i += blockDim.x)
        if ((i & 1) && ei32[i] != 0) bad = 1;
    bad = __syncthreads_or(bad);
    if (threadIdx.x == 0) g_idx64 = bad ? 0 : 1;
}

// ---------------- zero degree array ----------------
__global__ void zero_deg_kernel() {
    int i = blockIdx.x * blockDim.x + threadIdx.x;
    if (i < NN) g_deg[i] = 0;
}

// ---------------- decode edge_index -> int32 src/dst + dst histogram ----------------
__global__ __launch_bounds__(256) void prep_idx_kernel(const void* __restrict__ ei) {
    int e = blockIdx.x * blockDim.x + threadIdx.x;
    if (e >= EE) return;
    int s, d;
    if (g_idx64) {
        const long long* p = (const long long*)ei;
        s = (int)p[e]; d = (int)p[EE + e];
    } else {
        const int* p = (const int*)ei;
        s = p[e]; d = p[EE + e];
    }
    if ((unsigned)s >= NN) s = 0;
    if ((unsigned)d >= NN) d = 0;
    g_src[e] = s; g_dst[e] = d;
    atomicAdd(&g_deg[d], 1);
}

// ---------------- multi-block exclusive scan of g_deg ----------------
#define SCAN_B 1024
#define SCAN_NB ((NN + SCAN_B - 1) / SCAN_B)   // 98

// phase 1: per-block exclusive scan -> g_off (partial), block totals -> g_bsum
__global__ __launch_bounds__(SCAN_B) void scan1_kernel() {
    __shared__ int sdata[SCAN_B];
    int i = blockIdx.x * SCAN_B + threadIdx.x;
    int v = (i < NN) ? g_deg[i] : 0;
    sdata[threadIdx.x] = v;
    __syncthreads();
#pragma unroll
    for (int off = 1; off < SCAN_B; off <<= 1) {
        int t = (threadIdx.x >= off) ? sdata[threadIdx.x - off] : 0;
        __syncthreads();
        sdata[threadIdx.x] += t;
        __syncthreads();
    }
    if (i < NN) g_off[i] = sdata[threadIdx.x] - v;
    if (threadIdx.x == SCAN_B - 1) g_bsum[blockIdx.x] = sdata[SCAN_B - 1];
}

// phase 2: scan the 98 block sums (single tiny block)
__global__ __launch_bounds__(128) void scan2_kernel() {
    __shared__ int sdata[128];
    int v = (threadIdx.x < SCAN_NB) ? g_bsum[threadIdx.x] : 0;
    sdata[threadIdx.x] = v;
    __syncthreads();
#pragma unroll
    for (int off = 1; off < 128; off <<= 1) {
        int t = (threadIdx.x >= off) ? sdata[threadIdx.x - off] : 0;
        __syncthreads();
        sdata[threadIdx.x] += t;
        __syncthreads();
    }
    if (threadIdx.x < SCAN_NB) g_boff[threadIdx.x] = sdata[threadIdx.x] - v;
    if (threadIdx.x == 127) g_off[NN] = sdata[127];
}

// phase 3: add block offsets, init g_cur
__global__ __launch_bounds__(256) void scan3_kernel() {
    int i = blockIdx.x * blockDim.x + threadIdx.x;
    if (i >= NN) return;
    int o = g_off[i] + g_boff[i / SCAN_B];
    g_off[i] = o;
    g_cur[i] = o;
}

// ---------------- reorder edges by dst ----------------
__global__ __launch_bounds__(256) void reorder_kernel(const float* __restrict__ ew) {
    int e = blockIdx.x * blockDim.x + threadIdx.x;
    if (e >= EE) return;
    int d = g_dst[e];
    int pos = atomicAdd(&g_cur[d], 1);
    g_esrc[pos] = g_src[e];
    g_esw[pos]  = ew[e];
}

// ---------------- split weight[l] ([k][n]) -> transposed [n][k] hi/lo ----------------
__global__ void split_w1_kernel(const float* __restrict__ w,
                                unsigned short* __restrict__ hi,
                                unsigned short* __restrict__ lo) {
    int i = blockIdx.x * blockDim.x + threadIdx.x;
    if (i >= 3 * HH * HH) return;
    int l = i >> 14, rem = i & 16383;
    int k = rem >> 7, n = rem & 127;
    float f = w[i];
    unsigned h = bf16h(f);
    unsigned lb = bf16h(f - bf16f(h));
    int o = l * HH * HH + n * HH + k;
    hi[o] = (unsigned short)h;
    lo[o] = (unsigned short)lb;
}

// ---------------- split BOTH gru weight matrices in one launch ----------------
__global__ void split_w2_kernel(const float* __restrict__ wa, const float* __restrict__ wb,
                                unsigned short* __restrict__ hia, unsigned short* __restrict__ loa,
                                unsigned short* __restrict__ hib, unsigned short* __restrict__ lob) {
    int i = blockIdx.x * blockDim.x + threadIdx.x;
    int count = H3 * HH;
    if (i < count) {
        float f = wa[i];
        unsigned h = bf16h(f);
        hia[i] = (unsigned short)h;
        loa[i] = (unsigned short)bf16h(f - bf16f(h));
    } else if (i < 2 * count) {
        int j = i - count;
        float f = wb[j];
        unsigned h = bf16h(f);
        hib[j] = (unsigned short)h;
        lob[j] = (unsigned short)bf16h(f - bf16f(h));
    }
}

// ---------------- shared GEMM pieces ----------------
#define SAW 68
#define SA  (128 * SAW)
#define SB  (64 * SAW)
#define OFF_ALO SA
#define OFF_B   (2 * SA)
#define SMEM_WORDS (2 * SA + 4 * SB)
#define SMEM_BYTES (SMEM_WORDS * 4)  // 139264

__device__ __forceinline__ void mma_bf16(float* c, const unsigned* a, unsigned b0, unsigned b1) {
    asm volatile(
        "mma.sync.aligned.m16n8k16.row.col.f32.bf16.bf16.f32 "
        "{%0,%1,%2,%3}, {%4,%5,%6,%7}, {%8,%9}, {%0,%1,%2,%3};"
        : "+f"(c[0]), "+f"(c[1]), "+f"(c[2]), "+f"(c[3])
        : "r"(a[0]), "r"(a[1]), "r"(a[2]), "r"(a[3]), "r"(b0), "r"(b1));
}

// stage 128x128 fp32 A tile into smem as bf16 hi/lo
__device__ __forceinline__ void stage_A(const float* __restrict__ A, int nrows, int row0,
                                        unsigned* sAhi, unsigned* sAlo, int tid) {
#pragma unroll
    for (int r = 0; r < 16; r++) {
        int i = r * 256 + tid;
        int row = i >> 5, q = i & 31;
        float4 v;
        if (row0 + row < nrows) v = *(const float4*)&A[(size_t)(row0 + row) * HH + q * 4];
        else v = make_float4(0.f, 0.f, 0.f, 0.f);
        unsigned h0 = bf16h(v.x), h1 = bf16h(v.y), h2 = bf16h(v.z), h3 = bf16h(v.w);
        unsigned l0 = bf16h(v.x - bf16f(h0)), l1 = bf16h(v.y - bf16f(h1));
        unsigned l2 = bf16h(v.z - bf16f(h2)), l3 = bf16h(v.w - bf16f(h3));
        int o = row * SAW + q * 2;
        sAhi[o] = h0 | (h1 << 16); sAhi[o + 1] = h2 | (h3 << 16);
        sAlo[o] = l0 | (l1 << 16); sAlo[o + 1] = l2 | (l3 << 16);
    }
}

// compute one 128x64 tile: 8 k-steps, 3-term split
#define TILE_COMPUTE(accv, bHiAddr, bLoAddr)                                       \
    {                                                                              \
        _Pragma("unroll")                                                          \
        for (int s = 0; s < 8; s++) {                                              \
            const uint32_t sOff = (uint32_t)(s * 8) * 4;                           \
            unsigned ahi[2][4], alo[2][4];                                         \
            _Pragma("unroll")                                                      \
            for (int ma = 0; ma < 2; ma++) {                                       \
                const uint32_t rOff = (uint32_t)(ma * 16 * SAW) * 4;               \
                ldsm_x4(ahi[ma], aAddrHi0 + rOff + sOff);                          \
                ldsm_x4(alo[ma], aAddrLo0 + rOff + sOff);                          \
            }                                                                      \
            _Pragma("unroll")                                                      \
            for (int na = 0; na < 4; na++) {                                       \
                const uint32_t nOff = (uint32_t)(na * 8 * SAW) * 4;                \
                unsigned bh[2], bl[2];                                             \
                ldsm_x2(bh, (bHiAddr) + nOff + sOff);                              \
                ldsm_x2(bl, (bLoAddr) + nOff + sOff);                              \
                _Pragma("unroll")                                                  \
                for (int ma = 0; ma < 2; ma++) {                                   \
                    mma_bf16(accv[ma][na], ahi[ma], bh[0], bh[1]);                 \
                    mma_bf16(accv[ma][na], ahi[ma], bl[0], bl[1]);                 \
                    mma_bf16(accv[ma][na], alo[ma], bh[0], bh[1]);                 \
                }                                                                  \
            }                                                                      \
        }                                                                          \
    }

// ---------------- persistent-A GEMM, dual output sets (m + gh) ----------------
__global__ __launch_bounds__(256) void mma_gemm_persist(
    const float* __restrict__ A, int nrows,
    const unsigned short* __restrict__ B1h, const unsigned short* __restrict__ B1l,
    const float* __restrict__ bias1, float* __restrict__ C1, int ncols1, int nt1,
    const unsigned short* __restrict__ B2h, const unsigned short* __restrict__ B2l,
    const float* __restrict__ bias2, float* __restrict__ C2, int ncols2, int nt2)
{
    extern __shared__ __align__(16) unsigned sm[];
    unsigned* sAhi = sm;
    unsigned* sAlo = sm + OFF_ALO;
    const uint32_t smb = smem_u32(sm);

    const int tid = threadIdx.x, lane = tid & 31, wid = tid >> 5;
    const int lg = lane >> 2, t = lane & 3;
    const int wm = (wid & 3) * 32, wn = (wid >> 2) * 32;
    const int row0 = blockIdx.x * 128;
    const int NT = nt1 + nt2;

    stage_A(A, nrows, row0, sAhi, sAlo, tid);

    const int a_row_l = ((lane >> 3) & 1) * 8 + (lane & 7);
    const int a_kw_l  = ((lane >> 4) & 1) * 4;
    const int b_row_l = lane & 7;
    const int b_kw_l  = ((lane >> 3) & 1) * 4;
    const uint32_t aAddrHi0 = smb + (uint32_t)((wm + a_row_l) * SAW + a_kw_l) * 4;
    const uint32_t aAddrLo0 = aAddrHi0 + (uint32_t)OFF_ALO * 4;
    const uint32_t bAddrBase = (uint32_t)((wn + b_row_l) * SAW + b_kw_l) * 4;

    const int brow = tid >> 2, bq = tid & 3;
    const uint32_t bdw = (uint32_t)(brow * SAW + bq * 16) * 4;

    auto issueB = [&](int ti) {
        const unsigned short* Bh; const unsigned short* Bl; int col0;
        if (ti < nt1) { Bh = B1h; Bl = B1l; col0 = ti * 64; }
        else          { Bh = B2h; Bl = B2l; col0 = (ti - nt1) * 64; }
        int buf = ti & 1;
        uint32_t dsth = smb + (uint32_t)(OFF_B + buf * 2 * SB) * 4 + bdw;
        uint32_t dstl = dsth + (uint32_t)SB * 4;
        const uint4* srch = (const uint4*)Bh + (size_t)(col0 + brow) * 16 + bq * 4;
        const uint4* srcl = (const uint4*)Bl + (size_t)(col0 + brow) * 16 + bq * 4;
#pragma unroll
        for (int j = 0; j < 4; j++) {
            cpasync16(dsth + j * 16, srch + j);
            cpasync16(dstl + j * 16, srcl + j);
        }
    };

    issueB(0); CP_COMMIT();

    for (int ti = 0; ti < NT; ti++) {
        bool has_next = (ti + 1 < NT);
        if (has_next) { issueB(ti + 1); CP_COMMIT(); }
        if (has_next) CP_WAIT1(); else CP_WAIT0();
        __syncthreads();

        const uint32_t bHiAddr = smb + (uint32_t)(OFF_B + (ti & 1) * 2 * SB) * 4 + bAddrBase;
        const uint32_t bLoAddr = bHiAddr + (uint32_t)SB * 4;

        float acc[2][4][4];
#pragma unroll
        for (int i = 0; i < 2; i++)
#pragma unroll
            for (int j = 0; j < 4; j++)
#pragma unroll
                for (int q = 0; q < 4; q++) acc[i][j][q] = 0.f;

        TILE_COMPUTE(acc, bHiAddr, bLoAddr);

        const float* bias; float* C; int ncols, col0;
        if (ti < nt1) { bias = bias1; C = C1; ncols = ncols1; col0 = ti * 64; }
        else          { bias = bias2; C = C2; ncols = ncols2; col0 = (ti - nt1) * 64; }
#pragma unroll
        for (int ma = 0; ma < 2; ma++) {
#pragma unroll
            for (int na = 0; na < 4; na++) {
                int col = col0 + wn + na * 8 + t * 2;
                float b0 = bias ? bias[col] : 0.f;
                float b1 = bias ? bias[col + 1] : 0.f;
                int r0 = row0 + wm + ma * 16 + lg;
                if (r0 < nrows) {
                    float2 o = make_float2(acc[ma][na][0] + b0, acc[ma][na][1] + b1);
                    *(float2*)&C[(size_t)r0 * ncols + col] = o;
                }
                int r1 = r0 + 8;
                if (r1 < nrows) {
                    float2 o = make_float2(acc[ma][na][2] + b0, acc[ma][na][3] + b1);
                    *(float2*)&C[(size_t)r1 * ncols + col] = o;
                }
            }
        }
        __syncthreads();
    }
}

// ---------------- persistent-A GEMM with fused GRU (gi = A@w_ih^T + b_ih) ----------
__global__ __launch_bounds__(256) void mma_gemm_gru(
    const float* __restrict__ A, int nrows,
    const unsigned short* __restrict__ Bh16, const unsigned short* __restrict__ Bl16,
    const float* __restrict__ bias,
    const float* __restrict__ gh, const float* __restrict__ x, float* __restrict__ xout)
{
    extern __shared__ __align__(16) unsigned sm[];
    unsigned* sAhi = sm;
    unsigned* sAlo = sm + OFF_ALO;
    const uint32_t smb = smem_u32(sm);

    const int tid = threadIdx.x, lane = tid & 31, wid = tid >> 5;
    const int lg = lane >> 2, t = lane & 3;
    const int wm = (wid & 3) * 32, wn = (wid >> 2) * 32;
    const int row0 = blockIdx.x * 128;

    stage_A(A, nrows, row0, sAhi, sAlo, tid);

    const int a_row_l = ((lane >> 3) & 1) * 8 + (lane & 7);
    const int a_kw_l  = ((lane >> 4) & 1) * 4;
    const int b_row_l = lane & 7;
    const int b_kw_l  = ((lane >> 3) & 1) * 4;
    const uint32_t aAddrHi0 = smb + (uint32_t)((wm + a_row_l) * SAW + a_kw_l) * 4;
    const uint32_t aAddrLo0 = aAddrHi0 + (uint32_t)OFF_ALO * 4;
    const uint32_t bAddrBase = (uint32_t)((wn + b_row_l) * SAW + b_kw_l) * 4;

    const int brow = tid >> 2, bq = tid & 3;
    const uint32_t bdw = (uint32_t)(brow * SAW + bq * 16) * 4;

    auto tileCol = [](int s) { return (s % 3) * 128 + (s / 3) * 64; };

    auto issueB = [&](int s) {
        int col0 = tileCol(s);
        int buf = s & 1;
        uint32_t dsth = smb + (uint32_t)(OFF_B + buf * 2 * SB) * 4 + bdw;
        uint32_t dstl = dsth + (uint32_t)SB * 4;
        const uint4* srch = (const uint4*)Bh16 + (size_t)(col0 + brow) * 16 + bq * 4;
        const uint4* srcl = (const uint4*)Bl16 + (size_t)(col0 + brow) * 16 + bq * 4;
#pragma unroll
        for (int j = 0; j < 4; j++) {
            cpasync16(dsth + j * 16, srch + j);
            cpasync16(dstl + j * 16, srcl + j);
        }
    };

    issueB(0); CP_COMMIT();

    float acc[3][2][4][4];   // r, z, n accumulators for current group

    for (int group = 0; group < 2; group++) {
#pragma unroll
        for (int part = 0; part < 3; part++) {
            int s = group * 3 + part;
            bool has_next = (s + 1 < 6);
            if (has_next) { issueB(s + 1); CP_COMMIT(); }
            if (has_next) CP_WAIT1(); else CP_WAIT0();
            __syncthreads();

            const uint32_t bHiAddr = smb + (uint32_t)(OFF_B + (s & 1) * 2 * SB) * 4 + bAddrBase;
            const uint32_t bLoAddr = bHiAddr + (uint32_t)SB * 4;

#pragma unroll
            for (int i = 0; i < 2; i++)
#pragma unroll
                for (int j = 0; j < 4; j++)
#pragma unroll
                    for (int q = 0; q < 4; q++) acc[part][i][j][q] = 0.f;

            TILE_COMPUTE(acc[part], bHiAddr, bLoAddr);
            __syncthreads();
        }

        // ---- fused GRU epilogue for feature cols [group*64, group*64+64) ----
#pragma unroll
        for (int ma = 0; ma < 2; ma++) {
#pragma unroll
            for (int na = 0; na < 4; na++) {
                int col = group * 64 + wn + na * 8 + t * 2;     // 0..127
                float bR0 = bias[col],       bR1 = bias[col + 1];
                float bZ0 = bias[col + 128], bZ1 = bias[col + 129];
                float bN0 = bias[col + 256], bN1 = bias[col + 257];
#pragma unroll
                for (int half = 0; half < 2; half++) {
                    int row = row0 + wm + ma * 16 + lg + half * 8;
                    if (row >= nrows) continue;
                    int q0 = half * 2;
                    float giR0 = acc[0][ma][na][q0]     + bR0;
                    float giR1 = acc[0][ma][na][q0 + 1] + bR1;
                    float giZ0 = acc[1][ma][na][q0]     + bZ0;
                    float giZ1 = acc[1][ma][na][q0 + 1] + bZ1;
                    float giN0 = acc[2][ma][na][q0]     + bN0;
                    float giN1 = acc[2][ma][na][q0 + 1] + bN1;
                    const float* ghrow = gh + (size_t)row * H3;
                    float2 ghR = *(const float2*)&ghrow[col];
                    float2 ghZ = *(const float2*)&ghrow[col + 128];
                    float2 ghN = *(const float2*)&ghrow[col + 256];
                    float2 xv  = *(const float2*)&x[(size_t)row * HH + col];
                    float r0 = 1.f / (1.f + __expf(-(giR0 + ghR.x)));
                    float r1 = 1.f / (1.f + __expf(-(giR1 + ghR.y)));
                    float z0 = 1.f / (1.f + __expf(-(giZ0 + ghZ.x)));
                    float z1 = 1.f / (1.f + __expf(-(giZ1 + ghZ.y)));
                    float n0 = tanhf(giN0 + r0 * ghN.x);
                    float n1 = tanhf(giN1 + r1 * ghN.y);
                    float2 o = make_float2((1.f - z0) * n0 + z0 * xv.x,
                                           (1.f - z1) * n1 + z1 * xv.y);
                    *(float2*)&xout[(size_t)row * HH + col] = o;
                }
            }
        }
    }
}

// ---------------- CSR aggregate: warp per destination node ----------------
__global__ __launch_bounds__(256) void csr_agg_kernel(
    const float* __restrict__ m, float* __restrict__ agg)
{
    int warp = (int)((blockIdx.x * blockDim.x + threadIdx.x) >> 5);
    int lane = threadIdx.x & 31;
    if (warp >= NN) return;
    int e = g_off[warp], end = g_off[warp + 1];
    float4 acc = make_float4(0.f, 0.f, 0.f, 0.f);
    for (; e < end; e++) {
        int s = g_esrc[e];
        float w = g_esw[e];
        float4 v = *(const float4*)(m + (size_t)s * HH + lane * 4);
        acc.x += v.x * w; acc.y += v.y * w; acc.z += v.z * w; acc.w += v.w * w;
    }
    *(float4*)(agg + (size_t)warp * HH + lane * 4) = acc;
}

// ---------------- host ----------------
extern "C" void kernel_launch(void* const* d_in, const int* in_sizes, int n_in,
                              void* d_out, int out_size)
{
    const float* z = nullptr; const float* ew = nullptr; const void* ei = nullptr;
    const float* mats[3] = {nullptr, nullptr, nullptr}; int nmat = 0;
    const float* vecs[2] = {nullptr, nullptr};          int nvec = 0;
    for (int i = 0; i < n_in; i++) {
        int sz = in_sizes[i];
        if      (sz == NN * HH)      z  = (const float*)d_in[i];
        else if (sz == EE)           ew = (const float*)d_in[i];
        else if (sz == 2 * EE)       ei = d_in[i];
        else if (sz == 3 * HH * HH) { if (nmat < 3) mats[nmat++] = (const float*)d_in[i]; }
        else if (sz == 3 * HH)      { if (nvec < 2) vecs[nvec++] = (const float*)d_in[i]; }
    }
    if (!z  && n_in > 0) z  = (const float*)d_in[0];
    if (!ew && n_in > 1) ew = (const float*)d_in[1];
    if (nmat < 3) { mats[0] = (const float*)d_in[2]; mats[1] = (const float*)d_in[3]; mats[2] = (const float*)d_in[4]; }
    if (nvec < 2) { vecs[0] = (const float*)d_in[5]; vecs[1] = (const float*)d_in[6]; }
    if (!ei && n_in > 7) ei = d_in[7];

    const float* weight = mats[0];
    const float* w_ih   = mats[1];
    const float* w_hh   = mats[2];
    const float* b_ih   = vecs[0];
    const float* b_hh   = vecs[1];
    float*       out    = (float*)d_out;

    float *pm, *pagg, *pgh, *px;
    unsigned short *pB1h, *pB1l, *pIhh, *pIhl, *pHhh, *pHhl;
    cudaGetSymbolAddress((void**)&pm,   g_m);
    cudaGetSymbolAddress((void**)&pagg, g_agg);
    cudaGetSymbolAddress((void**)&pgh,  g_gh);
    cudaGetSymbolAddress((void**)&px,   g_x);
    cudaGetSymbolAddress((void**)&pB1h, g_B1hi);
    cudaGetSymbolAddress((void**)&pB1l, g_B1lo);
    cudaGetSymbolAddress((void**)&pIhh, g_Bihhi);
    cudaGetSymbolAddress((void**)&pIhl, g_Bihlo);
    cudaGetSymbolAddress((void**)&pHhh, g_Bhhhi);
    cudaGetSymbolAddress((void**)&pHhl, g_Bhhlo);

    static int smem_set = 0;
    if (!smem_set) {
        cudaFuncSetAttribute(mma_gemm_persist, cudaFuncAttributeMaxDynamicSharedMemorySize, SMEM_BYTES);
        cudaFuncSetAttribute(mma_gemm_gru,     cudaFuncAttributeMaxDynamicSharedMemorySize, SMEM_BYTES);
        smem_set = 1;
    }

    const int GMX = (NN + 127) / 128;                 // 782
    const int aggGrid = (NN * 32 + 255) / 256;        // warp per dst

    detect_idx_kernel<<<1, 256>>>((const int*)ei);
    zero_deg_kernel<<<(NN + 255) / 256, 256>>>();
    prep_idx_kernel<<<(EE + 255) / 256, 256>>>(ei);
    scan1_kernel<<<SCAN_NB, SCAN_B>>>();
    scan2_kernel<<<1, 128>>>();
    scan3_kernel<<<(NN + 255) / 256, 256>>>();
    reorder_kernel<<<(EE + 255) / 256, 256>>>(ew);
    split_w1_kernel<<<(3 * HH * HH + 255) / 256, 256>>>(weight, pB1h, pB1l);
    split_w2_kernel<<<(2 * H3 * HH + 255) / 256, 256>>>(w_ih, w_hh, pIhh, pIhl, pHhh, pHhl);

    const float* x = z;
    for (int l = 0; l < LL; l++) {
        // fused: m = x@W[l] (2 tiles) and gh = x@w_hh^T + b_hh (6 tiles); A staged once
        mma_gemm_persist<<<GMX, 256, SMEM_BYTES>>>(
            x, NN,
            pB1h + (size_t)l * HH * HH, pB1l + (size_t)l * HH * HH, nullptr, pm, HH, 2,
            pHhh, pHhl, b_hh, pgh, H3, 6);
        // agg = segment_sum(m[src] * ew, dst)  — CSR, no atomics, no zeroing
        csr_agg_kernel<<<aggGrid, 256>>>(pm, pagg);
        // gi GEMM + fused GRU -> next x
        float* xout = (l == LL - 1) ? out : px;
        mma_gemm_gru<<<GMX, 256, SMEM_BYTES>>>(
            pagg, NN, pIhh, pIhl, b_ih, pgh, x, xout);
        x = px;
    }
}

// round 17
// speedup vs baseline: 1.2118x; 1.0139x over previous
#include <cuda_runtime.h>
#include <cstdint>

#define NN 100000
#define EE 1600000
#define HH 128
#define H3 384
#define LL 3

// ---------------- scratch (static device globals; no allocation) ----------------
__device__ __align__(256) float g_m[(size_t)NN * HH];     // m = x @ W[l]
__device__ __align__(256) float g_agg[(size_t)NN * HH];   // aggregated messages
__device__ __align__(256) float g_gh[(size_t)NN * H3];    // x @ w_hh^T + b_hh
__device__ __align__(256) float g_x[(size_t)NN * HH];     // hidden state ping buffer
__device__ int g_idx64;
__device__ __align__(256) int g_src[EE];
__device__ __align__(256) int g_dst[EE];
// CSR by destination
__device__ __align__(256) int g_deg[NN];
__device__ __align__(256) int g_off[NN + 1];
__device__ __align__(256) int g_cur[NN];
__device__ __align__(256) int g_bsum[128];
__device__ __align__(256) int g_boff[128];
__device__ __align__(256) int g_esrc[EE];
__device__ __align__(256) float g_esw[EE];

// bf16 hi/lo split weights, stored [n][k] (k contiguous, K=128)
__device__ __align__(256) unsigned short g_B1hi[3 * HH * HH];
__device__ __align__(256) unsigned short g_B1lo[3 * HH * HH];
__device__ __align__(256) unsigned short g_Bihhi[H3 * HH];
__device__ __align__(256) unsigned short g_Bihlo[H3 * HH];
__device__ __align__(256) unsigned short g_Bhhhi[H3 * HH];
__device__ __align__(256) unsigned short g_Bhhlo[H3 * HH];

// ---------------- bf16 split helpers ----------------
__device__ __forceinline__ unsigned bf16h(float f) {
    unsigned x = __float_as_uint(f);
    return (x + 0x7fffu + ((x >> 16) & 1u)) >> 16;   // rn-even to bf16 bits
}
__device__ __forceinline__ float bf16f(unsigned b) { return __uint_as_float(b << 16); }

__device__ __forceinline__ uint32_t smem_u32(const void* p) {
    uint32_t a;
    asm("{ .reg .u64 t; cvta.to.shared.u64 t, %1; cvt.u32.u64 %0, t; }" : "=r"(a) : "l"(p));
    return a;
}
__device__ __forceinline__ void cpasync16(uint32_t dst, const void* src) {
    asm volatile("cp.async.cg.shared.global [%0], [%1], 16;" :: "r"(dst), "l"(src));
}
#define CP_COMMIT() asm volatile("cp.async.commit_group;" ::: "memory")
#define CP_WAIT1()  asm volatile("cp.async.wait_group 1;" ::: "memory")
#define CP_WAIT0()  asm volatile("cp.async.wait_group 0;" ::: "memory")

__device__ __forceinline__ void ldsm_x4(unsigned* r, uint32_t addr) {
    asm volatile("ldmatrix.sync.aligned.m8n8.x4.shared.b16 {%0,%1,%2,%3}, [%4];"
        : "=r"(r[0]), "=r"(r[1]), "=r"(r[2]), "=r"(r[3]) : "r"(addr));
}
__device__ __forceinline__ void ldsm_x2(unsigned* r, uint32_t addr) {
    asm volatile("ldmatrix.sync.aligned.m8n8.x2.shared.b16 {%0,%1}, [%2];"
        : "=r"(r[0]), "=r"(r[1]) : "r"(addr));
}

// ---------------- detect edge_index dtype ----------------
__global__ void detect_idx_kernel(const int* __restrict__ ei32) {
    int bad = 0;
    for (int i = threadIdx.x; i < 4096; i += blockDim.x)
        if ((i & 1) && ei32[i] != 0) bad = 1;
    bad = __syncthreads_or(bad);
    if (threadIdx.x == 0) g_idx64 = bad ? 0 : 1;
}

// ---------------- zero degree array ----------------
__global__ void zero_deg_kernel() {
    int i = blockIdx.x * blockDim.x + threadIdx.x;
    if (i < NN) g_deg[i] = 0;
}

// ---------------- decode edge_index -> int32 src/dst + dst histogram ----------------
__global__ __launch_bounds__(256) void prep_idx_kernel(const void* __restrict__ ei) {
    int e = blockIdx.x * blockDim.x + threadIdx.x;
    if (e >= EE) return;
    int s, d;
    if (g_idx64) {
        const long long* p = (const long long*)ei;
        s = (int)p[e]; d = (int)p[EE + e];
    } else {
        const int* p = (const int*)ei;
        s = p[e]; d = p[EE + e];
    }
    if ((unsigned)s >= NN) s = 0;
    if ((unsigned)d >= NN) d = 0;
    g_src[e] = s; g_dst[e] = d;
    atomicAdd(&g_deg[d], 1);
}

// ---------------- multi-block exclusive scan of g_deg ----------------
#define SCAN_B 1024
#define SCAN_NB ((NN + SCAN_B - 1) / SCAN_B)   // 98

__global__ __launch_bounds__(SCAN_B) void scan1_kernel() {
    __shared__ int sdata[SCAN_B];
    int i = blockIdx.x * SCAN_B + threadIdx.x;
    int v = (i < NN) ? g_deg[i] : 0;
    sdata[threadIdx.x] = v;
    __syncthreads();
#pragma unroll
    for (int off = 1; off < SCAN_B; off <<= 1) {
        int t = (threadIdx.x >= off) ? sdata[threadIdx.x - off] : 0;
        __syncthreads();
        sdata[threadIdx.x] += t;
        __syncthreads();
    }
    if (i < NN) g_off[i] = sdata[threadIdx.x] - v;
    if (threadIdx.x == SCAN_B - 1) g_bsum[blockIdx.x] = sdata[SCAN_B - 1];
}

__global__ __launch_bounds__(128) void scan2_kernel() {
    __shared__ int sdata[128];
    int v = (threadIdx.x < SCAN_NB) ? g_bsum[threadIdx.x] : 0;
    sdata[threadIdx.x] = v;
    __syncthreads();
#pragma unroll
    for (int off = 1; off < 128; off <<= 1) {
        int t = (threadIdx.x >= off) ? sdata[threadIdx.x - off] : 0;
        __syncthreads();
        sdata[threadIdx.x] += t;
        __syncthreads();
    }
    if (threadIdx.x < SCAN_NB) g_boff[threadIdx.x] = sdata[threadIdx.x] - v;
    if (threadIdx.x == 127) g_off[NN] = sdata[127];
}

__global__ __launch_bounds__(256) void scan3_kernel() {
    int i = blockIdx.x * blockDim.x + threadIdx.x;
    if (i >= NN) return;
    int o = g_off[i] + g_boff[i / SCAN_B];
    g_off[i] = o;
    g_cur[i] = o;
}

// ---------------- reorder edges by dst ----------------
__global__ __launch_bounds__(256) void reorder_kernel(const float* __restrict__ ew) {
    int e = blockIdx.x * blockDim.x + threadIdx.x;
    if (e >= EE) return;
    int d = g_dst[e];
    int pos = atomicAdd(&g_cur[d], 1);
    g_esrc[pos] = g_src[e];
    g_esw[pos]  = ew[e];
}

// ---------------- split weight[l] ([k][n]) -> transposed [n][k] hi/lo ----------------
__global__ void split_w1_kernel(const float* __restrict__ w,
                                unsigned short* __restrict__ hi,
                                unsigned short* __restrict__ lo) {
    int i = blockIdx.x * blockDim.x + threadIdx.x;
    if (i >= 3 * HH * HH) return;
    int l = i >> 14, rem = i & 16383;
    int k = rem >> 7, n = rem & 127;
    float f = w[i];
    unsigned h = bf16h(f);
    unsigned lb = bf16h(f - bf16f(h));
    int o = l * HH * HH + n * HH + k;
    hi[o] = (unsigned short)h;
    lo[o] = (unsigned short)lb;
}

// ---------------- split BOTH gru weight matrices in one launch ----------------
__global__ void split_w2_kernel(const float* __restrict__ wa, const float* __restrict__ wb,
                                unsigned short* __restrict__ hia, unsigned short* __restrict__ loa,
                                unsigned short* __restrict__ hib, unsigned short* __restrict__ lob) {
    int i = blockIdx.x * blockDim.x + threadIdx.x;
    int count = H3 * HH;
    if (i < count) {
        float f = wa[i];
        unsigned h = bf16h(f);
        hia[i] = (unsigned short)h;
        loa[i] = (unsigned short)bf16h(f - bf16f(h));
    } else if (i < 2 * count) {
        int j = i - count;
        float f = wb[j];
        unsigned h = bf16h(f);
        hib[j] = (unsigned short)h;
        lob[j] = (unsigned short)bf16h(f - bf16f(h));
    }
}

// ---------------- shared GEMM pieces ----------------
#define SAW 68
#define SA  (128 * SAW)
#define SB  (64 * SAW)
#define OFF_ALO SA
#define OFF_B   (2 * SA)
#define SMEM_WORDS (2 * SA + 4 * SB)
#define SMEM_BYTES (SMEM_WORDS * 4)  // 139264

__device__ __forceinline__ void mma_bf16(float* c, const unsigned* a, unsigned b0, unsigned b1) {
    asm volatile(
        "mma.sync.aligned.m16n8k16.row.col.f32.bf16.bf16.f32 "
        "{%0,%1,%2,%3}, {%4,%5,%6,%7}, {%8,%9}, {%0,%1,%2,%3};"
        : "+f"(c[0]), "+f"(c[1]), "+f"(c[2]), "+f"(c[3])
        : "r"(a[0]), "r"(a[1]), "r"(a[2]), "r"(a[3]), "r"(b0), "r"(b1));
}

// stage 128x128 fp32 A tile into smem as bf16 hi/lo
__device__ __forceinline__ void stage_A(const float* __restrict__ A, int nrows, int row0,
                                        unsigned* sAhi, unsigned* sAlo, int tid) {
#pragma unroll
    for (int r = 0; r < 16; r++) {
        int i = r * 256 + tid;
        int row = i >> 5, q = i & 31;
        float4 v;
        if (row0 + row < nrows) v = *(const float4*)&A[(size_t)(row0 + row) * HH + q * 4];
        else v = make_float4(0.f, 0.f, 0.f, 0.f);
        unsigned h0 = bf16h(v.x), h1 = bf16h(v.y), h2 = bf16h(v.z), h3 = bf16h(v.w);
        unsigned l0 = bf16h(v.x - bf16f(h0)), l1 = bf16h(v.y - bf16f(h1));
        unsigned l2 = bf16h(v.z - bf16f(h2)), l3 = bf16h(v.w - bf16f(h3));
        int o = row * SAW + q * 2;
        sAhi[o] = h0 | (h1 << 16); sAhi[o + 1] = h2 | (h3 << 16);
        sAlo[o] = l0 | (l1 << 16); sAlo[o + 1] = l2 | (l3 << 16);
    }
}

// compute one 128x64 tile: 8 k-steps, 3-term split
#define TILE_COMPUTE(accv, bHiAddr, bLoAddr)                                       \
    {                                                                              \
        _Pragma("unroll")                                                          \
        for (int s = 0; s < 8; s++) {                                              \
            const uint32_t sOff = (uint32_t)(s * 8) * 4;                           \
            unsigned ahi[2][4], alo[2][4];                                         \
            _Pragma("unroll")                                                      \
            for (int ma = 0; ma < 2; ma++) {                                       \
                const uint32_t rOff = (uint32_t)(ma * 16 * SAW) * 4;               \
                ldsm_x4(ahi[ma], aAddrHi0 + rOff + sOff);                          \
                ldsm_x4(alo[ma], aAddrLo0 + rOff + sOff);                          \
            }                                                                      \
            _Pragma("unroll")                                                      \
            for (int na = 0; na < 4; na++) {                                       \
                const uint32_t nOff = (uint32_t)(na * 8 * SAW) * 4;                \
                unsigned bh[2], bl[2];                                             \
                ldsm_x2(bh, (bHiAddr) + nOff + sOff);                              \
                ldsm_x2(bl, (bLoAddr) + nOff + sOff);                              \
                _Pragma("unroll")                                                  \
                for (int ma = 0; ma < 2; ma++) {                                   \
                    mma_bf16(accv[ma][na], ahi[ma], bh[0], bh[1]);                 \
                    mma_bf16(accv[ma][na], ahi[ma], bl[0], bl[1]);                 \
                    mma_bf16(accv[ma][na], alo[ma], bh[0], bh[1]);                 \
                }                                                                  \
            }                                                                      \
        }                                                                          \
    }

// ---------------- persistent-A GEMM, dual output sets ----------------
__global__ __launch_bounds__(256) void mma_gemm_persist(
    const float* __restrict__ A, int nrows,
    const unsigned short* __restrict__ B1h, const unsigned short* __restrict__ B1l,
    const float* __restrict__ bias1, float* __restrict__ C1, int ncols1, int nt1,
    const unsigned short* __restrict__ B2h, const unsigned short* __restrict__ B2l,
    const float* __restrict__ bias2, float* __restrict__ C2, int ncols2, int nt2)
{
    extern __shared__ __align__(16) unsigned sm[];
    unsigned* sAhi = sm;
    unsigned* sAlo = sm + OFF_ALO;
    const uint32_t smb = smem_u32(sm);

    const int tid = threadIdx.x, lane = tid & 31, wid = tid >> 5;
    const int lg = lane >> 2, t = lane & 3;
    const int wm = (wid & 3) * 32, wn = (wid >> 2) * 32;
    const int row0 = blockIdx.x * 128;
    const int NT = nt1 + nt2;

    stage_A(A, nrows, row0, sAhi, sAlo, tid);

    const int a_row_l = ((lane >> 3) & 1) * 8 + (lane & 7);
    const int a_kw_l  = ((lane >> 4) & 1) * 4;
    const int b_row_l = lane & 7;
    const int b_kw_l  = ((lane >> 3) & 1) * 4;
    const uint32_t aAddrHi0 = smb + (uint32_t)((wm + a_row_l) * SAW + a_kw_l) * 4;
    const uint32_t aAddrLo0 = aAddrHi0 + (uint32_t)OFF_ALO * 4;
    const uint32_t bAddrBase = (uint32_t)((wn + b_row_l) * SAW + b_kw_l) * 4;

    const int brow = tid >> 2, bq = tid & 3;
    const uint32_t bdw = (uint32_t)(brow * SAW + bq * 16) * 4;

    auto issueB = [&](int ti) {
        const unsigned short* Bh; const unsigned short* Bl; int col0;
        if (ti < nt1) { Bh = B1h; Bl = B1l; col0 = ti * 64; }
        else          { Bh = B2h; Bl = B2l; col0 = (ti - nt1) * 64; }
        int buf = ti & 1;
        uint32_t dsth = smb + (uint32_t)(OFF_B + buf * 2 * SB) * 4 + bdw;
        uint32_t dstl = dsth + (uint32_t)SB * 4;
        const uint4* srch = (const uint4*)Bh + (size_t)(col0 + brow) * 16 + bq * 4;
        const uint4* srcl = (const uint4*)Bl + (size_t)(col0 + brow) * 16 + bq * 4;
#pragma unroll
        for (int j = 0; j < 4; j++) {
            cpasync16(dsth + j * 16, srch + j);
            cpasync16(dstl + j * 16, srcl + j);
        }
    };

    issueB(0); CP_COMMIT();

    for (int ti = 0; ti < NT; ti++) {
        bool has_next = (ti + 1 < NT);
        if (has_next) { issueB(ti + 1); CP_COMMIT(); }
        if (has_next) CP_WAIT1(); else CP_WAIT0();
        __syncthreads();

        const uint32_t bHiAddr = smb + (uint32_t)(OFF_B + (ti & 1) * 2 * SB) * 4 + bAddrBase;
        const uint32_t bLoAddr = bHiAddr + (uint32_t)SB * 4;

        float acc[2][4][4];
#pragma unroll
        for (int i = 0; i < 2; i++)
#pragma unroll
            for (int j = 0; j < 4; j++)
#pragma unroll
                for (int q = 0; q < 4; q++) acc[i][j][q] = 0.f;

        TILE_COMPUTE(acc, bHiAddr, bLoAddr);

        const float* bias; float* C; int ncols, col0;
        if (ti < nt1) { bias = bias1; C = C1; ncols = ncols1; col0 = ti * 64; }
        else          { bias = bias2; C = C2; ncols = ncols2; col0 = (ti - nt1) * 64; }
#pragma unroll
        for (int ma = 0; ma < 2; ma++) {
#pragma unroll
            for (int na = 0; na < 4; na++) {
                int col = col0 + wn + na * 8 + t * 2;
                float b0 = bias ? bias[col] : 0.f;
                float b1 = bias ? bias[col + 1] : 0.f;
                int r0 = row0 + wm + ma * 16 + lg;
                if (r0 < nrows) {
                    float2 o = make_float2(acc[ma][na][0] + b0, acc[ma][na][1] + b1);
                    *(float2*)&C[(size_t)r0 * ncols + col] = o;
                }
                int r1 = r0 + 8;
                if (r1 < nrows) {
                    float2 o = make_float2(acc[ma][na][2] + b0, acc[ma][na][3] + b1);
                    *(float2*)&C[(size_t)r1 * ncols + col] = o;
                }
            }
        }
        __syncthreads();
    }
}

// ---------------- persistent-A GEMM with fused GRU ----------
__global__ __launch_bounds__(256) void mma_gemm_gru(
    const float* __restrict__ A, int nrows,
    const unsigned short* __restrict__ Bh16, const unsigned short* __restrict__ Bl16,
    const float* __restrict__ bias,
    const float* __restrict__ gh, const float* __restrict__ x, float* __restrict__ xout)
{
    extern __shared__ __align__(16) unsigned sm[];
    unsigned* sAhi = sm;
    unsigned* sAlo = sm + OFF_ALO;
    const uint32_t smb = smem_u32(sm);

    const int tid = threadIdx.x, lane = tid & 31, wid = tid >> 5;
    const int lg = lane >> 2, t = lane & 3;
    const int wm = (wid & 3) * 32, wn = (wid >> 2) * 32;
    const int row0 = blockIdx.x * 128;

    stage_A(A, nrows, row0, sAhi, sAlo, tid);

    const int a_row_l = ((lane >> 3) & 1) * 8 + (lane & 7);
    const int a_kw_l  = ((lane >> 4) & 1) * 4;
    const int b_row_l = lane & 7;
    const int b_kw_l  = ((lane >> 3) & 1) * 4;
    const uint32_t aAddrHi0 = smb + (uint32_t)((wm + a_row_l) * SAW + a_kw_l) * 4;
    const uint32_t aAddrLo0 = aAddrHi0 + (uint32_t)OFF_ALO * 4;
    const uint32_t bAddrBase = (uint32_t)((wn + b_row_l) * SAW + b_kw_l) * 4;

    const int brow = tid >> 2, bq = tid & 3;
    const uint32_t bdw = (uint32_t)(brow * SAW + bq * 16) * 4;

    auto tileCol = [](int s) { return (s % 3) * 128 + (s / 3) * 64; };

    auto issueB = [&](int s) {
        int col0 = tileCol(s);
        int buf = s & 1;
        uint32_t dsth = smb + (uint32_t)(OFF_B + buf * 2 * SB) * 4 + bdw;
        uint32_t dstl = dsth + (uint32_t)SB * 4;
        const uint4* srch = (const uint4*)Bh16 + (size_t)(col0 + brow) * 16 + bq * 4;
        const uint4* srcl = (const uint4*)Bl16 + (size_t)(col0 + brow) * 16 + bq * 4;
#pragma unroll
        for (int j = 0; j < 4; j++) {
            cpasync16(dsth + j * 16, srch + j);
            cpasync16(dstl + j * 16, srcl + j);
        }
    };

    issueB(0); CP_COMMIT();

    float acc[3][2][4][4];   // r, z, n accumulators for current group

    for (int group = 0; group < 2; group++) {
#pragma unroll
        for (int part = 0; part < 3; part++) {
            int s = group * 3 + part;
            bool has_next = (s + 1 < 6);
            if (has_next) { issueB(s + 1); CP_COMMIT(); }
            if (has_next) CP_WAIT1(); else CP_WAIT0();
            __syncthreads();

            const uint32_t bHiAddr = smb + (uint32_t)(OFF_B + (s & 1) * 2 * SB) * 4 + bAddrBase;
            const uint32_t bLoAddr = bHiAddr + (uint32_t)SB * 4;

#pragma unroll
            for (int i = 0; i < 2; i++)
#pragma unroll
                for (int j = 0; j < 4; j++)
#pragma unroll
                    for (int q = 0; q < 4; q++) acc[part][i][j][q] = 0.f;

            TILE_COMPUTE(acc[part], bHiAddr, bLoAddr);
            __syncthreads();
        }

        // ---- fused GRU epilogue for feature cols [group*64, group*64+64) ----
#pragma unroll
        for (int ma = 0; ma < 2; ma++) {
#pragma unroll
            for (int na = 0; na < 4; na++) {
                int col = group * 64 + wn + na * 8 + t * 2;     // 0..127
                float bR0 = bias[col],       bR1 = bias[col + 1];
                float bZ0 = bias[col + 128], bZ1 = bias[col + 129];
                float bN0 = bias[col + 256], bN1 = bias[col + 257];
#pragma unroll
                for (int half = 0; half < 2; half++) {
                    int row = row0 + wm + ma * 16 + lg + half * 8;
                    if (row >= nrows) continue;
                    int q0 = half * 2;
                    float giR0 = acc[0][ma][na][q0]     + bR0;
                    float giR1 = acc[0][ma][na][q0 + 1] + bR1;
                    float giZ0 = acc[1][ma][na][q0]     + bZ0;
                    float giZ1 = acc[1][ma][na][q0 + 1] + bZ1;
                    float giN0 = acc[2][ma][na][q0]     + bN0;
                    float giN1 = acc[2][ma][na][q0 + 1] + bN1;
                    const float* ghrow = gh + (size_t)row * H3;
                    float2 ghR = *(const float2*)&ghrow[col];
                    float2 ghZ = *(const float2*)&ghrow[col + 128];
                    float2 ghN = *(const float2*)&ghrow[col + 256];
                    float2 xv  = *(const float2*)&x[(size_t)row * HH + col];
                    float r0 = 1.f / (1.f + __expf(-(giR0 + ghR.x)));
                    float r1 = 1.f / (1.f + __expf(-(giR1 + ghR.y)));
                    float z0 = 1.f / (1.f + __expf(-(giZ0 + ghZ.x)));
                    float z1 = 1.f / (1.f + __expf(-(giZ1 + ghZ.y)));
                    float n0 = tanhf(giN0 + r0 * ghN.x);
                    float n1 = tanhf(giN1 + r1 * ghN.y);
                    float2 o = make_float2((1.f - z0) * n0 + z0 * xv.x,
                                           (1.f - z1) * n1 + z1 * xv.y);
                    *(float2*)&xout[(size_t)row * HH + col] = o;
                }
            }
        }
    }
}

// ---------------- CSR aggregate: warp per destination node ----------------
__global__ __launch_bounds__(256) void csr_agg_kernel(
    const float* __restrict__ m, float* __restrict__ agg)
{
    int warp = (int)((blockIdx.x * blockDim.x + threadIdx.x) >> 5);
    int lane = threadIdx.x & 31;
    if (warp >= NN) return;
    int e = g_off[warp], end = g_off[warp + 1];
    float4 acc = make_float4(0.f, 0.f, 0.f, 0.f);
    for (; e < end; e++) {
        int s = g_esrc[e];
        float w = g_esw[e];
        float4 v = *(const float4*)(m + (size_t)s * HH + lane * 4);
        acc.x += v.x * w; acc.y += v.y * w; acc.z += v.z * w; acc.w += v.w * w;
    }
    *(float4*)(agg + (size_t)warp * HH + lane * 4) = acc;
}

// ---------------- host ----------------
extern "C" void kernel_launch(void* const* d_in, const int* in_sizes, int n_in,
                              void* d_out, int out_size)
{
    const float* z = nullptr; const float* ew = nullptr; const void* ei = nullptr;
    const float* mats[3] = {nullptr, nullptr, nullptr}; int nmat = 0;
    const float* vecs[2] = {nullptr, nullptr};          int nvec = 0;
    for (int i = 0; i < n_in; i++) {
        int sz = in_sizes[i];
        if      (sz == NN * HH)      z  = (const float*)d_in[i];
        else if (sz == EE)           ew = (const float*)d_in[i];
        else if (sz == 2 * EE)       ei = d_in[i];
        else if (sz == 3 * HH * HH) { if (nmat < 3) mats[nmat++] = (const float*)d_in[i]; }
        else if (sz == 3 * HH)      { if (nvec < 2) vecs[nvec++] = (const float*)d_in[i]; }
    }
    if (!z  && n_in > 0) z  = (const float*)d_in[0];
    if (!ew && n_in > 1) ew = (const float*)d_in[1];
    if (nmat < 3) { mats[0] = (const float*)d_in[2]; mats[1] = (const float*)d_in[3]; mats[2] = (const float*)d_in[4]; }
    if (nvec < 2) { vecs[0] = (const float*)d_in[5]; vecs[1] = (const float*)d_in[6]; }
    if (!ei && n_in > 7) ei = d_in[7];

    const float* weight = mats[0];
    const float* w_ih   = mats[1];
    const float* w_hh   = mats[2];
    const float* b_ih   = vecs[0];
    const float* b_hh   = vecs[1];
    float*       out    = (float*)d_out;

    float *pm, *pagg, *pgh, *px;
    unsigned short *pB1h, *pB1l, *pIhh, *pIhl, *pHhh, *pHhl;
    cudaGetSymbolAddress((void**)&pm,   g_m);
    cudaGetSymbolAddress((void**)&pagg, g_agg);
    cudaGetSymbolAddress((void**)&pgh,  g_gh);
    cudaGetSymbolAddress((void**)&px,   g_x);
    cudaGetSymbolAddress((void**)&pB1h, g_B1hi);
    cudaGetSymbolAddress((void**)&pB1l, g_B1lo);
    cudaGetSymbolAddress((void**)&pIhh, g_Bihhi);
    cudaGetSymbolAddress((void**)&pIhl, g_Bihlo);
    cudaGetSymbolAddress((void**)&pHhh, g_Bhhhi);
    cudaGetSymbolAddress((void**)&pHhl, g_Bhhlo);

    static int init_done = 0;
    static cudaStream_t s1;
    static cudaEvent_t evX, evGH;
    if (!init_done) {
        cudaFuncSetAttribute(mma_gemm_persist, cudaFuncAttributeMaxDynamicSharedMemorySize, SMEM_BYTES);
        cudaFuncSetAttribute(mma_gemm_gru,     cudaFuncAttributeMaxDynamicSharedMemorySize, SMEM_BYTES);
        cudaStreamCreateWithFlags(&s1, cudaStreamNonBlocking);
        cudaEventCreateWithFlags(&evX,  cudaEventDisableTiming);
        cudaEventCreateWithFlags(&evGH, cudaEventDisableTiming);
        init_done = 1;
    }

    const int GMX = (NN + 127) / 128;                 // 782
    const int aggGrid = (NN * 32 + 255) / 256;        // warp per dst

    detect_idx_kernel<<<1, 256>>>((const int*)ei);
    zero_deg_kernel<<<(NN + 255) / 256, 256>>>();
    prep_idx_kernel<<<(EE + 255) / 256, 256>>>(ei);
    scan1_kernel<<<SCAN_NB, SCAN_B>>>();
    scan2_kernel<<<1, 128>>>();
    scan3_kernel<<<(NN + 255) / 256, 256>>>();
    reorder_kernel<<<(EE + 255) / 256, 256>>>(ew);
    split_w1_kernel<<<(3 * HH * HH + 255) / 256, 256>>>(weight, pB1h, pB1l);
    split_w2_kernel<<<(2 * H3 * HH + 255) / 256, 256>>>(w_ih, w_hh, pIhh, pIhl, pHhh, pHhl);

    const float* x = z;
    for (int l = 0; l < LL; l++) {
        // fork: gh GEMM (off critical path) on s1
        cudaEventRecord(evX, 0);
        cudaStreamWaitEvent(s1, evX, 0);
        mma_gemm_persist<<<GMX, 256, SMEM_BYTES, s1>>>(
            x, NN,
            pHhh, pHhl, b_hh, pgh, H3, 6,
            nullptr, nullptr, nullptr, nullptr, 0, 0);
        cudaEventRecord(evGH, s1);

        // critical path on stream 0: m GEMM (2 tiles) -> CSR aggregate
        mma_gemm_persist<<<GMX, 256, SMEM_BYTES>>>(
            x, NN,
            pB1h + (size_t)l * HH * HH, pB1l + (size_t)l * HH * HH, nullptr, pm, HH, 2,
            nullptr, nullptr, nullptr, nullptr, 0, 0);
        csr_agg_kernel<<<aggGrid, 256>>>(pm, pagg);

        // join: gi GEMM + fused GRU needs agg (stream0) and gh (s1)
        cudaStreamWaitEvent(0, evGH, 0);
        float* xout = (l == LL - 1) ? out : px;
        mma_gemm_gru<<<GMX, 256, SMEM_BYTES>>>(
            pagg, NN, pIhh, pIhl, b_ih, pgh, x, xout);
        x = px;
    }
}